// round 2
// baseline (speedup 1.0000x reference)
#include <cuda_runtime.h>

// ---------------------------------------------------------------------------
// MultiUniverseToposAttention  B=1 S=512 H=8 DH=64 DM=512 TOP_K=2
// Pipeline:
//   1) gemm_qkv:  Q,K,V = x @ sig(W{q,k,v})^T          (fused sigmoid-of-W)
//   2) router:    logits -> softmax -> top2 -> gate weights per (s,h)
//   3) rope_sig:  RoPE(Q,K) -> sigmoid -> head-major Qs,Ks; V -> head-major
//   4) attn:      truth[q,k] = 1 - mean_d relu(Qs-Ks); out = (truth@V)/rowsum
//                 gated: skip (q,h) pairs with zero gate; writes G[s][h*64+d]
//   5) gemm_out:  out = G @ sig(Wo)^T
// ---------------------------------------------------------------------------

#define S_   512
#define DM_  512
#define H_   8
#define DH_  64
#define HALF_ 32

__device__ float g_Q [S_ * DM_];
__device__ float g_K [S_ * DM_];
__device__ float g_V [S_ * DM_];
__device__ float g_Qs[H_][S_][DH_];
__device__ float g_Ks[H_][S_][DH_];
__device__ float g_Vh[H_][S_][DH_];
__device__ float g_gate[S_][H_];
__device__ float g_G [S_ * DM_];

__device__ __forceinline__ float sigf(float x) {
    return 1.0f / (1.0f + __expf(-x));
}

// ---------------------------------------------------------------------------
// Tiled fp32 GEMM: C[m][n] = sum_k A[m][k] * sig(W[n][k]),  all dims 512,
// 64x64 block tile, 256 threads, 4x4 microtile, BK=16.
// ---------------------------------------------------------------------------
__device__ __forceinline__ void gemm_sig_body(const float* __restrict__ A,
                                              const float* __restrict__ W,
                                              float* __restrict__ C) {
    __shared__ float As[16][68];
    __shared__ float Bs[16][68];
    const int K = DM_;
    const int m0 = blockIdx.y * 64;
    const int n0 = blockIdx.x * 64;
    const int t  = threadIdx.x;
    const int tx = t & 15, ty = t >> 4;
    const int lrow = t >> 2, lc = (t & 3) << 2;

    float acc[4][4] = {};

    for (int k0 = 0; k0 < K; k0 += 16) {
        float4 av = *(const float4*)&A[(m0 + lrow) * K + k0 + lc];
        float4 wv = *(const float4*)&W[(n0 + lrow) * K + k0 + lc];
        As[lc + 0][lrow] = av.x;
        As[lc + 1][lrow] = av.y;
        As[lc + 2][lrow] = av.z;
        As[lc + 3][lrow] = av.w;
        Bs[lc + 0][lrow] = sigf(wv.x);
        Bs[lc + 1][lrow] = sigf(wv.y);
        Bs[lc + 2][lrow] = sigf(wv.z);
        Bs[lc + 3][lrow] = sigf(wv.w);
        __syncthreads();
#pragma unroll
        for (int kk = 0; kk < 16; kk++) {
            float4 a4 = *(const float4*)&As[kk][ty << 2];
            float4 b4 = *(const float4*)&Bs[kk][tx << 2];
            float a[4] = {a4.x, a4.y, a4.z, a4.w};
            float b[4] = {b4.x, b4.y, b4.z, b4.w};
#pragma unroll
            for (int i = 0; i < 4; i++)
#pragma unroll
                for (int j = 0; j < 4; j++)
                    acc[i][j] = fmaf(a[i], b[j], acc[i][j]);
        }
        __syncthreads();
    }
#pragma unroll
    for (int i = 0; i < 4; i++) {
        float4 o = make_float4(acc[i][0], acc[i][1], acc[i][2], acc[i][3]);
        *(float4*)&C[(m0 + (ty << 2) + i) * DM_ + n0 + (tx << 2)] = o;
    }
}

__global__ void __launch_bounds__(256)
k_gemm_qkv(const float* __restrict__ x,
           const float* __restrict__ Wq,
           const float* __restrict__ Wk,
           const float* __restrict__ Wv) {
    const float* W;
    float* C;
    if (blockIdx.z == 0)      { W = Wq; C = g_Q; }
    else if (blockIdx.z == 1) { W = Wk; C = g_K; }
    else                      { W = Wv; C = g_V; }
    gemm_sig_body(x, W, C);
}

__global__ void __launch_bounds__(256)
k_gemm_out(const float* __restrict__ Wo, float* __restrict__ out) {
    gemm_sig_body(g_G, Wo, out);
}

// ---------------------------------------------------------------------------
// Router: per token, 8 dot products (len 512) -> softmax -> top2 -> gate
// One block (256 threads) per token; warp h handles head h.
// ---------------------------------------------------------------------------
__global__ void __launch_bounds__(256)
k_router(const float* __restrict__ x, const float* __restrict__ Wr) {
    const int s = blockIdx.x;
    const int t = threadIdx.x;
    const int h = t >> 5, lane = t & 31;

    const float* xs = x + s * DM_;
    const float* wr = Wr + h * DM_;
    float acc = 0.f;
    for (int d = lane; d < DM_; d += 32)
        acc += xs[d] * sigf(wr[d]);
#pragma unroll
    for (int o = 16; o > 0; o >>= 1)
        acc += __shfl_xor_sync(0xFFFFFFFFu, acc, o);

    __shared__ float lg[H_];
    if (lane == 0) lg[h] = acc;
    __syncthreads();

    if (t == 0) {
        float m = lg[0];
#pragma unroll
        for (int i = 1; i < H_; i++) m = fmaxf(m, lg[i]);
        float e[H_];
        float Z = 0.f;
#pragma unroll
        for (int i = 0; i < H_; i++) { e[i] = expf(lg[i] - m); Z += e[i]; }
        // top-2 (first occurrence on ties, matching jax.lax.top_k)
        int i0 = 0;
#pragma unroll
        for (int i = 1; i < H_; i++) if (e[i] > e[i0]) i0 = i;
        int i1 = (i0 == 0) ? 1 : 0;
#pragma unroll
        for (int i = 0; i < H_; i++) if (i != i0 && e[i] > e[i1]) i1 = i;
        float p0 = e[i0] / Z, p1 = e[i1] / Z;
        float inv = 1.0f / (p0 + p1 + 1e-9f);
#pragma unroll
        for (int i = 0; i < H_; i++) g_gate[s][i] = 0.f;
        g_gate[s][i0] = p0 * inv;
        g_gate[s][i1] = p1 * inv;
    }
}

// ---------------------------------------------------------------------------
// RoPE + sigmoid for Q,K; transpose all of Q,K,V to head-major [h][s][d].
// One block (256 threads) per token: thread = (head, pair).
// ---------------------------------------------------------------------------
__global__ void __launch_bounds__(256)
k_rope_sig(const float* __restrict__ fc, const float* __restrict__ fs) {
    const int s = blockIdx.x;
    const int t = threadIdx.x;
    const int h = t >> 5, p = t & 31;

    const float c  = fc[s * HALF_ + p];
    const float sn = fs[s * HALF_ + p];
    const int base = s * DM_ + h * DH_ + 2 * p;

    float q0 = g_Q[base], q1 = g_Q[base + 1];
    float k0 = g_K[base], k1 = g_K[base + 1];
    float qr0 = q0 * c - q1 * sn, qr1 = q0 * sn + q1 * c;
    float kr0 = k0 * c - k1 * sn, kr1 = k0 * sn + k1 * c;
    g_Qs[h][s][2 * p]     = sigf(qr0);
    g_Qs[h][s][2 * p + 1] = sigf(qr1);
    g_Ks[h][s][2 * p]     = sigf(kr0);
    g_Ks[h][s][2 * p + 1] = sigf(kr1);

    // V transpose: 512 elems per token, 2 per thread
#pragma unroll
    for (int j = t; j < DM_; j += 256) {
        int h2 = j >> 6, d = j & 63;
        g_Vh[h2][s][d] = g_V[s * DM_ + j];
    }
}

// ---------------------------------------------------------------------------
// Attention: block = (q_tile of 32, head). truth = 1 - mean_d relu(Qs - Ks),
// out = (truth @ V) / (rowsum + 1e-9), gated by g_gate (skip inactive q).
// ---------------------------------------------------------------------------
__global__ void __launch_bounds__(256)
k_attn() {
    const int h  = blockIdx.y;
    const int q0 = blockIdx.x * 32;
    const int t  = threadIdx.x;

    __shared__ float Qs_s[32][64];
    __shared__ float Ks_s[32][65];   // pad 65: conflict-free lane-per-k reads
    __shared__ float Vs_s[32][64];
    __shared__ float Tr  [32][33];
    __shared__ float rs_s[32];
    __shared__ float wq_s[32];

    // load Q tile + gates + init rowsum
    for (int j = t; j < 32 * 64; j += 256) {
        int r = j >> 6, d = j & 63;
        Qs_s[r][d] = g_Qs[h][q0 + r][d];
    }
    if (t < 32) {
        wq_s[t] = g_gate[q0 + t][h];
        rs_s[t] = 0.f;
    }
    __syncthreads();

    const int qf = t >> 3;        // query owned in AV phase
    const int dg = t & 7;         // dim group (8 floats)
    float acc[8] = {};
    const bool qf_active = (wq_s[qf] != 0.f);

    for (int kt = 0; kt < 16; kt++) {
        const int k0 = kt * 32;
        for (int j = t; j < 32 * 64; j += 256) {
            int r = j >> 6, d = j & 63;
            Ks_s[r][d] = g_Ks[h][k0 + r][d];
            Vs_s[r][d] = g_Vh[h][k0 + r][d];
        }
        __syncthreads();

        // truth tile: 1024 pairs, 4 per thread; warp-uniform q -> uniform skip
#pragma unroll
        for (int i = 0; i < 4; i++) {
            int p = t + 256 * i;
            int q = p >> 5, k = p & 31;
            if (wq_s[q] != 0.f) {
                float a = 0.f;
#pragma unroll
                for (int d = 0; d < 64; d++)
                    a += fmaxf(Qs_s[q][d] - Ks_s[k][d], 0.f);
                Tr[q][k] = 1.0f - a * (1.0f / 64.0f);
            } else {
                Tr[q][k] = 0.f;
            }
        }
        __syncthreads();

        if (t < 32) {
            float r = 0.f;
#pragma unroll
            for (int k = 0; k < 32; k++) r += Tr[t][k];
            rs_s[t] += r;
        }

        if (qf_active) {
#pragma unroll
            for (int k = 0; k < 32; k++) {
                float tv = Tr[qf][k];
#pragma unroll
                for (int i = 0; i < 8; i++)
                    acc[i] += tv * Vs_s[k][(dg << 3) + i];
            }
        }
        __syncthreads();
    }

    float w = wq_s[qf];
    float invr = qf_active ? (w / (rs_s[qf] + 1e-9f)) : 0.f;
#pragma unroll
    for (int i = 0; i < 8; i++)
        g_G[(q0 + qf) * DM_ + h * DH_ + (dg << 3) + i] = acc[i] * invr;
}

// ---------------------------------------------------------------------------
extern "C" void kernel_launch(void* const* d_in, const int* in_sizes, int n_in,
                              void* d_out, int out_size) {
    const float* x  = (const float*)d_in[0];
    const float* fc = (const float*)d_in[1];
    const float* fs = (const float*)d_in[2];
    const float* Wq = (const float*)d_in[3];
    const float* Wk = (const float*)d_in[4];
    const float* Wv = (const float*)d_in[5];
    const float* Wo = (const float*)d_in[6];
    const float* Wr = (const float*)d_in[7];
    float* out = (float*)d_out;

    k_gemm_qkv<<<dim3(8, 8, 3), 256>>>(x, Wq, Wk, Wv);
    k_router  <<<S_, 256>>>(x, Wr);
    k_rope_sig<<<S_, 256>>>(fc, fs);
    k_attn    <<<dim3(16, H_), 256>>>();
    k_gemm_out<<<dim3(8, 8), 256>>>(Wo, out);
}

// round 4
// speedup vs baseline: 1.0905x; 1.0905x over previous
#include <cuda_runtime.h>

// ---------------------------------------------------------------------------
// MultiUniverseToposAttention  B=1 S=512 H=8 DH=64 DM=512 TOP_K=2
//   1) gemm_qkv:  Q,K,V = x @ sig(W{q,k,v})^T
//   2) router:    logits -> softmax -> top2 -> gate weights per (s,h)
//   3) rope_sig:  RoPE(Q,K) -> sigmoid -> head-major Qs,Ks; V -> head-major
//   4) attn (split-K x4): partial truth@V + partial rowsums per split
//   5) norm:      combine splits, apply gate -> G
//   6) gemm_out:  out = G @ sig(Wo)^T
// ---------------------------------------------------------------------------

#define S_   512
#define DM_  512
#define H_   8
#define DH_  64
#define HALF_ 32
#define NSPL 4
#define KPS  (S_ / NSPL)     // 128 keys per split

__device__ float g_Q [S_ * DM_];
__device__ float g_K [S_ * DM_];
__device__ float g_V [S_ * DM_];
__device__ float g_Qs[H_][S_][DH_];
__device__ float g_Ks[H_][S_][DH_];
__device__ float g_Vh[H_][S_][DH_];
__device__ float g_gate[S_][H_];
__device__ float g_G [S_ * DM_];
__device__ float g_pacc[NSPL][S_][DM_];    // split partial (truth@V), head-major in DM
__device__ float g_prs [NSPL][S_][H_];     // split partial rowsums

__device__ __forceinline__ float sigf(float x) {
    return 1.0f / (1.0f + __expf(-x));
}

// ---------------------------------------------------------------------------
// Tiled fp32 GEMM: C[m][n] = sum_k A[m][k] * sig(W[n][k]), dims 512,
// 64x64 tile, 256 threads, 4x4 microtile, BK=16.
// ---------------------------------------------------------------------------
__device__ __forceinline__ void gemm_sig_body(const float* __restrict__ A,
                                              const float* __restrict__ W,
                                              float* __restrict__ C) {
    __shared__ float As[16][68];
    __shared__ float Bs[16][68];
    const int K = DM_;
    const int m0 = blockIdx.y * 64;
    const int n0 = blockIdx.x * 64;
    const int t  = threadIdx.x;
    const int tx = t & 15, ty = t >> 4;
    const int lrow = t >> 2, lc = (t & 3) << 2;

    float acc[4][4] = {};

    for (int k0 = 0; k0 < K; k0 += 16) {
        float4 av = *(const float4*)&A[(m0 + lrow) * K + k0 + lc];
        float4 wv = *(const float4*)&W[(n0 + lrow) * K + k0 + lc];
        As[lc + 0][lrow] = av.x;
        As[lc + 1][lrow] = av.y;
        As[lc + 2][lrow] = av.z;
        As[lc + 3][lrow] = av.w;
        Bs[lc + 0][lrow] = sigf(wv.x);
        Bs[lc + 1][lrow] = sigf(wv.y);
        Bs[lc + 2][lrow] = sigf(wv.z);
        Bs[lc + 3][lrow] = sigf(wv.w);
        __syncthreads();
#pragma unroll
        for (int kk = 0; kk < 16; kk++) {
            float4 a4 = *(const float4*)&As[kk][ty << 2];
            float4 b4 = *(const float4*)&Bs[kk][tx << 2];
            float a[4] = {a4.x, a4.y, a4.z, a4.w};
            float b[4] = {b4.x, b4.y, b4.z, b4.w};
#pragma unroll
            for (int i = 0; i < 4; i++)
#pragma unroll
                for (int j = 0; j < 4; j++)
                    acc[i][j] = fmaf(a[i], b[j], acc[i][j]);
        }
        __syncthreads();
    }
#pragma unroll
    for (int i = 0; i < 4; i++) {
        float4 o = make_float4(acc[i][0], acc[i][1], acc[i][2], acc[i][3]);
        *(float4*)&C[(m0 + (ty << 2) + i) * DM_ + n0 + (tx << 2)] = o;
    }
}

__global__ void __launch_bounds__(256)
k_gemm_qkv(const float* __restrict__ x,
           const float* __restrict__ Wq,
           const float* __restrict__ Wk,
           const float* __restrict__ Wv) {
    const float* W;
    float* C;
    if (blockIdx.z == 0)      { W = Wq; C = g_Q; }
    else if (blockIdx.z == 1) { W = Wk; C = g_K; }
    else                      { W = Wv; C = g_V; }
    gemm_sig_body(x, W, C);
}

__global__ void __launch_bounds__(256)
k_gemm_out(const float* __restrict__ Wo, float* __restrict__ out) {
    gemm_sig_body(g_G, Wo, out);
}

// ---------------------------------------------------------------------------
// Router
// ---------------------------------------------------------------------------
__global__ void __launch_bounds__(256)
k_router(const float* __restrict__ x, const float* __restrict__ Wr) {
    const int s = blockIdx.x;
    const int t = threadIdx.x;
    const int h = t >> 5, lane = t & 31;

    const float* xs = x + s * DM_;
    const float* wr = Wr + h * DM_;
    float acc = 0.f;
    for (int d = lane; d < DM_; d += 32)
        acc += xs[d] * sigf(wr[d]);
#pragma unroll
    for (int o = 16; o > 0; o >>= 1)
        acc += __shfl_xor_sync(0xFFFFFFFFu, acc, o);

    __shared__ float lg[H_];
    if (lane == 0) lg[h] = acc;
    __syncthreads();

    if (t == 0) {
        float m = lg[0];
#pragma unroll
        for (int i = 1; i < H_; i++) m = fmaxf(m, lg[i]);
        float e[H_];
        float Z = 0.f;
#pragma unroll
        for (int i = 0; i < H_; i++) { e[i] = expf(lg[i] - m); Z += e[i]; }
        int i0 = 0;
#pragma unroll
        for (int i = 1; i < H_; i++) if (e[i] > e[i0]) i0 = i;
        int i1 = (i0 == 0) ? 1 : 0;
#pragma unroll
        for (int i = 0; i < H_; i++) if (i != i0 && e[i] > e[i1]) i1 = i;
        float p0 = e[i0] / Z, p1 = e[i1] / Z;
        float inv = 1.0f / (p0 + p1 + 1e-9f);
#pragma unroll
        for (int i = 0; i < H_; i++) g_gate[s][i] = 0.f;
        g_gate[s][i0] = p0 * inv;
        g_gate[s][i1] = p1 * inv;
    }
}

// ---------------------------------------------------------------------------
// RoPE + sigmoid + head-major transpose
// ---------------------------------------------------------------------------
__global__ void __launch_bounds__(256)
k_rope_sig(const float* __restrict__ fc, const float* __restrict__ fs) {
    const int s = blockIdx.x;
    const int t = threadIdx.x;
    const int h = t >> 5, p = t & 31;

    const float c  = fc[s * HALF_ + p];
    const float sn = fs[s * HALF_ + p];
    const int base = s * DM_ + h * DH_ + 2 * p;

    float q0 = g_Q[base], q1 = g_Q[base + 1];
    float k0 = g_K[base], k1 = g_K[base + 1];
    float qr0 = q0 * c - q1 * sn, qr1 = q0 * sn + q1 * c;
    float kr0 = k0 * c - k1 * sn, kr1 = k0 * sn + k1 * c;
    g_Qs[h][s][2 * p]     = sigf(qr0);
    g_Qs[h][s][2 * p + 1] = sigf(qr1);
    g_Ks[h][s][2 * p]     = sigf(kr0);
    g_Ks[h][s][2 * p + 1] = sigf(kr1);

#pragma unroll
    for (int j = t; j < DM_; j += 256) {
        int h2 = j >> 6, d = j & 63;
        g_Vh[h2][s][d] = g_V[s * DM_ + j];
    }
}

// ---------------------------------------------------------------------------
// Attention, split-K x NSPL.
// Block = (q_tile 32, head, split). 256 threads.
// Truth phase: 2q x 2k register microtile, float4 over d.
// AV phase: thread (qf, dg) accumulates 8 output dims.
// ---------------------------------------------------------------------------
__global__ void __launch_bounds__(256)
k_attn() {
    const int h  = blockIdx.y;
    const int q0 = blockIdx.x * 32;
    const int z  = blockIdx.z;
    const int t  = threadIdx.x;

    __shared__ float Qs_s[32][68];
    __shared__ float Ks_s[32][68];
    __shared__ float Vs_s[32][68];
    __shared__ float Tr  [32][33];
    __shared__ float rs_s[32];
    __shared__ float wq_s[32];

    // load Q tile (float4, padded rows)
#pragma unroll
    for (int j = t; j < 32 * 16; j += 256) {
        int r = j >> 4, c4 = (j & 15) << 2;
        float4 v = *(const float4*)&g_Qs[h][q0 + r][c4];
        *(float4*)&Qs_s[r][c4] = v;
    }
    if (t < 32) {
        wq_s[t] = g_gate[q0 + t][h];
        rs_s[t] = 0.f;
    }
    __syncthreads();

    const int qq = t >> 4, kk = t & 15;     // truth microtile coords
    const int qa = 2 * qq, qb = qa + 1;
    const int ka = 2 * kk, kb = ka + 1;

    const int qf = t >> 3;                  // AV phase query row
    const int dg = (t & 7) << 3;            // AV phase dim group (8 floats)
    float acc[8] = {};
    const bool qf_active = (wq_s[qf] != 0.f);
    const bool pair_active = (wq_s[qa] != 0.f) || (wq_s[qb] != 0.f);

    for (int kt = 0; kt < KPS / 32; kt++) {
        const int k0 = z * KPS + kt * 32;
        __syncthreads();                    // protect Tr/Ks/Vs from prev iter
#pragma unroll
        for (int j = t; j < 32 * 16; j += 256) {
            int r = j >> 4, c4 = (j & 15) << 2;
            *(float4*)&Ks_s[r][c4] = *(const float4*)&g_Ks[h][k0 + r][c4];
            *(float4*)&Vs_s[r][c4] = *(const float4*)&g_Vh[h][k0 + r][c4];
        }
        __syncthreads();

        // truth: 2q x 2k microtile, float4 over d
        if (pair_active) {
            float s00 = 0.f, s01 = 0.f, s10 = 0.f, s11 = 0.f;
#pragma unroll
            for (int d = 0; d < 64; d += 4) {
                float4 A0 = *(const float4*)&Qs_s[qa][d];
                float4 A1 = *(const float4*)&Qs_s[qb][d];
                float4 B0 = *(const float4*)&Ks_s[ka][d];
                float4 B1 = *(const float4*)&Ks_s[kb][d];
                s00 += fmaxf(A0.x - B0.x, 0.f) + fmaxf(A0.y - B0.y, 0.f)
                     + fmaxf(A0.z - B0.z, 0.f) + fmaxf(A0.w - B0.w, 0.f);
                s01 += fmaxf(A0.x - B1.x, 0.f) + fmaxf(A0.y - B1.y, 0.f)
                     + fmaxf(A0.z - B1.z, 0.f) + fmaxf(A0.w - B1.w, 0.f);
                s10 += fmaxf(A1.x - B0.x, 0.f) + fmaxf(A1.y - B0.y, 0.f)
                     + fmaxf(A1.z - B0.z, 0.f) + fmaxf(A1.w - B0.w, 0.f);
                s11 += fmaxf(A1.x - B1.x, 0.f) + fmaxf(A1.y - B1.y, 0.f)
                     + fmaxf(A1.z - B1.z, 0.f) + fmaxf(A1.w - B1.w, 0.f);
            }
            const float c = 1.0f / 64.0f;
            Tr[qa][ka] = 1.0f - s00 * c;
            Tr[qa][kb] = 1.0f - s01 * c;
            Tr[qb][ka] = 1.0f - s10 * c;
            Tr[qb][kb] = 1.0f - s11 * c;
        }
        __syncthreads();

        if (t < 32 && wq_s[t] != 0.f) {
            float r = 0.f;
#pragma unroll
            for (int k = 0; k < 32; k++) r += Tr[t][k];
            rs_s[t] += r;
        }

        if (qf_active) {
#pragma unroll
            for (int k = 0; k < 32; k++) {
                float tv = Tr[qf][k];
                float4 v0 = *(const float4*)&Vs_s[k][dg];
                float4 v1 = *(const float4*)&Vs_s[k][dg + 4];
                acc[0] = fmaf(tv, v0.x, acc[0]);
                acc[1] = fmaf(tv, v0.y, acc[1]);
                acc[2] = fmaf(tv, v0.z, acc[2]);
                acc[3] = fmaf(tv, v0.w, acc[3]);
                acc[4] = fmaf(tv, v1.x, acc[4]);
                acc[5] = fmaf(tv, v1.y, acc[5]);
                acc[6] = fmaf(tv, v1.z, acc[6]);
                acc[7] = fmaf(tv, v1.w, acc[7]);
            }
        }
    }
    __syncthreads();

    // store split partials (zeros for inactive rows)
    float4 o0 = make_float4(acc[0], acc[1], acc[2], acc[3]);
    float4 o1 = make_float4(acc[4], acc[5], acc[6], acc[7]);
    *(float4*)&g_pacc[z][q0 + qf][h * DH_ + dg]     = o0;
    *(float4*)&g_pacc[z][q0 + qf][h * DH_ + dg + 4] = o1;
    if (t < 32) g_prs[z][q0 + t][h] = rs_s[t];
}

// ---------------------------------------------------------------------------
// Combine splits + gate -> G
// ---------------------------------------------------------------------------
__global__ void __launch_bounds__(256)
k_norm() {
    const int s = blockIdx.x;
    const int t = threadIdx.x;
#pragma unroll
    for (int j = t; j < DM_; j += 256) {
        int h = j >> 6;
        float gate = g_gate[s][h];
        float v = 0.f;
        if (gate != 0.f) {
            float rs = g_prs[0][s][h] + g_prs[1][s][h]
                     + g_prs[2][s][h] + g_prs[3][s][h];
            float a  = g_pacc[0][s][j] + g_pacc[1][s][j]
                     + g_pacc[2][s][j] + g_pacc[3][s][j];
            v = a * gate / (rs + 1e-9f);
        }
        g_G[s * DM_ + j] = v;
    }
}

// ---------------------------------------------------------------------------
extern "C" void kernel_launch(void* const* d_in, const int* in_sizes, int n_in,
                              void* d_out, int out_size) {
    const float* x  = (const float*)d_in[0];
    const float* fc = (const float*)d_in[1];
    const float* fs = (const float*)d_in[2];
    const float* Wq = (const float*)d_in[3];
    const float* Wk = (const float*)d_in[4];
    const float* Wv = (const float*)d_in[5];
    const float* Wo = (const float*)d_in[6];
    const float* Wr = (const float*)d_in[7];
    float* out = (float*)d_out;

    k_gemm_qkv<<<dim3(8, 8, 3), 256>>>(x, Wq, Wk, Wv);
    k_router  <<<S_, 256>>>(x, Wr);
    k_rope_sig<<<S_, 256>>>(fc, fs);
    k_attn    <<<dim3(16, H_, NSPL), 256>>>();
    k_norm    <<<S_, 256>>>();
    k_gemm_out<<<dim3(8, 8), 256>>>(Wo, out);
}

// round 5
// speedup vs baseline: 1.1642x; 1.0676x over previous
#include <cuda_runtime.h>

// ---------------------------------------------------------------------------
// MultiUniverseToposAttention  B=1 S=512 H=8 DH=64 DM=512 TOP_K=2
//   1) gemm_qkv:  Q,K,V = x @ sig(W{q,k,v})^T
//   2) router:    logits -> softmax -> top2 -> gate weights per (s,h)
//   3) rope_sig:  RoPE(Q,K) -> sigmoid -> head-major Qs,Ks; V -> head-major
//                 + per-key Ksum[h][s] = sum_d Ks[h][s][d]
//   4) compact:   per-head list of queries with nonzero gate (ballot scan)
//   5) attn (split-K x8, compacted): truth = 1 - (sum_d max(q,k) - Ksum)/64
//   6) norm:      combine splits, apply gate -> G
//   7) gemm_out:  out = G @ sig(Wo)^T
// ---------------------------------------------------------------------------

#define S_   512
#define DM_  512
#define H_   8
#define DH_  64
#define HALF_ 32
#define NSPL 8
#define KPS  (S_ / NSPL)     // 64 keys per split

__device__ float g_Q [S_ * DM_];
__device__ float g_K [S_ * DM_];
__device__ float g_V [S_ * DM_];
__device__ float g_Qs[H_][S_][DH_];
__device__ float g_Ks[H_][S_][DH_];
__device__ float g_Vh[H_][S_][DH_];
__device__ float g_Ksum[H_][S_];
__device__ float g_gate[S_][H_];
__device__ int   g_qidx[H_][S_];
__device__ int   g_qcnt[H_];
__device__ float g_G [S_ * DM_];
__device__ float g_pacc[NSPL][S_][DM_];    // split partial (truth@V)
__device__ float g_prs [NSPL][S_][H_];     // split partial rowsums

__device__ __forceinline__ float sigf(float x) {
    return 1.0f / (1.0f + __expf(-x));
}

// ---------------------------------------------------------------------------
// Tiled fp32 GEMM: C[m][n] = sum_k A[m][k] * sig(W[n][k]), dims 512,
// 64x64 tile, 256 threads, 4x4 microtile, BK=16.
// ---------------------------------------------------------------------------
__device__ __forceinline__ void gemm_sig_body(const float* __restrict__ A,
                                              const float* __restrict__ W,
                                              float* __restrict__ C) {
    __shared__ float As[16][68];
    __shared__ float Bs[16][68];
    const int K = DM_;
    const int m0 = blockIdx.y * 64;
    const int n0 = blockIdx.x * 64;
    const int t  = threadIdx.x;
    const int tx = t & 15, ty = t >> 4;
    const int lrow = t >> 2, lc = (t & 3) << 2;

    float acc[4][4] = {};

    for (int k0 = 0; k0 < K; k0 += 16) {
        float4 av = *(const float4*)&A[(m0 + lrow) * K + k0 + lc];
        float4 wv = *(const float4*)&W[(n0 + lrow) * K + k0 + lc];
        As[lc + 0][lrow] = av.x;
        As[lc + 1][lrow] = av.y;
        As[lc + 2][lrow] = av.z;
        As[lc + 3][lrow] = av.w;
        Bs[lc + 0][lrow] = sigf(wv.x);
        Bs[lc + 1][lrow] = sigf(wv.y);
        Bs[lc + 2][lrow] = sigf(wv.z);
        Bs[lc + 3][lrow] = sigf(wv.w);
        __syncthreads();
#pragma unroll
        for (int kk = 0; kk < 16; kk++) {
            float4 a4 = *(const float4*)&As[kk][ty << 2];
            float4 b4 = *(const float4*)&Bs[kk][tx << 2];
            float a[4] = {a4.x, a4.y, a4.z, a4.w};
            float b[4] = {b4.x, b4.y, b4.z, b4.w};
#pragma unroll
            for (int i = 0; i < 4; i++)
#pragma unroll
                for (int j = 0; j < 4; j++)
                    acc[i][j] = fmaf(a[i], b[j], acc[i][j]);
        }
        __syncthreads();
    }
#pragma unroll
    for (int i = 0; i < 4; i++) {
        float4 o = make_float4(acc[i][0], acc[i][1], acc[i][2], acc[i][3]);
        *(float4*)&C[(m0 + (ty << 2) + i) * DM_ + n0 + (tx << 2)] = o;
    }
}

__global__ void __launch_bounds__(256)
k_gemm_qkv(const float* __restrict__ x,
           const float* __restrict__ Wq,
           const float* __restrict__ Wk,
           const float* __restrict__ Wv) {
    const float* W;
    float* C;
    if (blockIdx.z == 0)      { W = Wq; C = g_Q; }
    else if (blockIdx.z == 1) { W = Wk; C = g_K; }
    else                      { W = Wv; C = g_V; }
    gemm_sig_body(x, W, C);
}

__global__ void __launch_bounds__(256)
k_gemm_out(const float* __restrict__ Wo, float* __restrict__ out) {
    gemm_sig_body(g_G, Wo, out);
}

// ---------------------------------------------------------------------------
// Router
// ---------------------------------------------------------------------------
__global__ void __launch_bounds__(256)
k_router(const float* __restrict__ x, const float* __restrict__ Wr) {
    const int s = blockIdx.x;
    const int t = threadIdx.x;
    const int h = t >> 5, lane = t & 31;

    const float* xs = x + s * DM_;
    const float* wr = Wr + h * DM_;
    float acc = 0.f;
    for (int d = lane; d < DM_; d += 32)
        acc += xs[d] * sigf(wr[d]);
#pragma unroll
    for (int o = 16; o > 0; o >>= 1)
        acc += __shfl_xor_sync(0xFFFFFFFFu, acc, o);

    __shared__ float lg[H_];
    if (lane == 0) lg[h] = acc;
    __syncthreads();

    if (t == 0) {
        float m = lg[0];
#pragma unroll
        for (int i = 1; i < H_; i++) m = fmaxf(m, lg[i]);
        float e[H_];
        float Z = 0.f;
#pragma unroll
        for (int i = 0; i < H_; i++) { e[i] = expf(lg[i] - m); Z += e[i]; }
        int i0 = 0;
#pragma unroll
        for (int i = 1; i < H_; i++) if (e[i] > e[i0]) i0 = i;
        int i1 = (i0 == 0) ? 1 : 0;
#pragma unroll
        for (int i = 0; i < H_; i++) if (i != i0 && e[i] > e[i1]) i1 = i;
        float p0 = e[i0] / Z, p1 = e[i1] / Z;
        float inv = 1.0f / (p0 + p1 + 1e-9f);
#pragma unroll
        for (int i = 0; i < H_; i++) g_gate[s][i] = 0.f;
        g_gate[s][i0] = p0 * inv;
        g_gate[s][i1] = p1 * inv;
    }
}

// ---------------------------------------------------------------------------
// RoPE + sigmoid + head-major transpose + Ksum
// ---------------------------------------------------------------------------
__global__ void __launch_bounds__(256)
k_rope_sig(const float* __restrict__ fc, const float* __restrict__ fs) {
    const int s = blockIdx.x;
    const int t = threadIdx.x;
    const int h = t >> 5, p = t & 31;

    const float c  = fc[s * HALF_ + p];
    const float sn = fs[s * HALF_ + p];
    const int base = s * DM_ + h * DH_ + 2 * p;

    float q0 = g_Q[base], q1 = g_Q[base + 1];
    float k0 = g_K[base], k1 = g_K[base + 1];
    float qr0 = q0 * c - q1 * sn, qr1 = q0 * sn + q1 * c;
    float kr0 = k0 * c - k1 * sn, kr1 = k0 * sn + k1 * c;
    float ks0 = sigf(kr0), ks1 = sigf(kr1);
    g_Qs[h][s][2 * p]     = sigf(qr0);
    g_Qs[h][s][2 * p + 1] = sigf(qr1);
    g_Ks[h][s][2 * p]     = ks0;
    g_Ks[h][s][2 * p + 1] = ks1;

    // Ksum[h][s] = sum_d Ks (warp reduce, warp == head)
    float v = ks0 + ks1;
#pragma unroll
    for (int o = 16; o > 0; o >>= 1)
        v += __shfl_xor_sync(0xFFFFFFFFu, v, o);
    if (p == 0) g_Ksum[h][s] = v;

#pragma unroll
    for (int j = t; j < DM_; j += 256) {
        int h2 = j >> 6, d = j & 63;
        g_Vh[h2][s][d] = g_V[s * DM_ + j];
    }
}

// ---------------------------------------------------------------------------
// Compaction: per head, ordered list of queries with nonzero gate.
// Single block, 256 threads (8 warps x 64 tokens each), ballot + popc scan.
// ---------------------------------------------------------------------------
__global__ void __launch_bounds__(256)
k_compact() {
    const int t = threadIdx.x;
    const int lane = t & 31, w = t >> 5;    // 8 warps
    __shared__ int swc[8];

    for (int h = 0; h < H_; h++) {
        const int s0 = w * 64 + lane;
        const int s1 = s0 + 32;
        const int f0 = (g_gate[s0][h] != 0.f) ? 1 : 0;
        const int f1 = (g_gate[s1][h] != 0.f) ? 1 : 0;
        const unsigned b0 = __ballot_sync(0xFFFFFFFFu, f0);
        const unsigned b1 = __ballot_sync(0xFFFFFFFFu, f1);
        if (lane == 0) swc[w] = __popc(b0) + __popc(b1);
        __syncthreads();
        int pre = 0;
#pragma unroll
        for (int i = 0; i < 8; i++) if (i < w) pre += swc[i];
        const unsigned lm = (1u << lane) - 1u;
        if (f0) g_qidx[h][pre + __popc(b0 & lm)] = s0;
        if (f1) g_qidx[h][pre + __popc(b0) + __popc(b1 & lm)] = s1;
        if (t == 0) {
            int tot = 0;
#pragma unroll
            for (int i = 0; i < 8; i++) tot += swc[i];
            g_qcnt[h] = tot;
        }
        __syncthreads();
    }
}

// ---------------------------------------------------------------------------
// Attention, compacted queries, split-K x NSPL.
// Block = (compacted q_tile 32, head, split). 256 threads.
// truth[q,k] = 1 - (sum_d max(Qs,Ks) - Ksum_k)/64   (== 1 - mean relu(q-k))
// ---------------------------------------------------------------------------
__global__ void __launch_bounds__(256)
k_attn() {
    const int h   = blockIdx.y;
    const int cnt = g_qcnt[h];
    const int q0  = blockIdx.x * 32;
    if (q0 >= cnt) return;
    const int nq  = min(32, cnt - q0);
    const int z   = blockIdx.z;
    const int t   = threadIdx.x;

    __shared__ float Qs_s[32][68];
    __shared__ float Ks_s[32][68];
    __shared__ float Vs_s[32][68];
    __shared__ float Tr  [32][33];
    __shared__ float rs_s[32];
    __shared__ float wq_s[32];
    __shared__ float ksum_s[32];
    __shared__ int   sidx[32];

    if (t < 32) {
        int s = g_qidx[h][q0 + ((t < nq) ? t : 0)];   // dup-pad tail rows
        sidx[t] = s;
        wq_s[t] = (t < nq) ? g_gate[s][h] : 0.f;
        rs_s[t] = 0.f;
    }
    __syncthreads();

    // load (gathered) Q tile rows
#pragma unroll
    for (int j = t; j < 32 * 16; j += 256) {
        int r = j >> 4, c4 = (j & 15) << 2;
        *(float4*)&Qs_s[r][c4] = *(const float4*)&g_Qs[h][sidx[r]][c4];
    }

    const int qq = t >> 4, kk = t & 15;     // truth microtile coords
    const int qa = 2 * qq, qb = qa + 1;
    const int ka = 2 * kk, kb = ka + 1;

    const int qf = t >> 3;                  // AV phase query row
    const int dg = (t & 7) << 3;            // AV phase dim group (8 floats)
    float acc[8] = {};
    const bool qf_active = (qf < nq);

    for (int kt = 0; kt < KPS / 32; kt++) {
        const int k0 = z * KPS + kt * 32;
        __syncthreads();
#pragma unroll
        for (int j = t; j < 32 * 16; j += 256) {
            int r = j >> 4, c4 = (j & 15) << 2;
            *(float4*)&Ks_s[r][c4] = *(const float4*)&g_Ks[h][k0 + r][c4];
            *(float4*)&Vs_s[r][c4] = *(const float4*)&g_Vh[h][k0 + r][c4];
        }
        if (t < 32) ksum_s[t] = g_Ksum[h][k0 + t];
        __syncthreads();

        // truth: 2q x 2k microtile via sum-of-max identity
        {
            float s00 = 0.f, s01 = 0.f, s10 = 0.f, s11 = 0.f;
#pragma unroll
            for (int d = 0; d < 64; d += 4) {
                float4 A0 = *(const float4*)&Qs_s[qa][d];
                float4 A1 = *(const float4*)&Qs_s[qb][d];
                float4 B0 = *(const float4*)&Ks_s[ka][d];
                float4 B1 = *(const float4*)&Ks_s[kb][d];
                s00 += fmaxf(A0.x, B0.x) + fmaxf(A0.y, B0.y)
                     + fmaxf(A0.z, B0.z) + fmaxf(A0.w, B0.w);
                s01 += fmaxf(A0.x, B1.x) + fmaxf(A0.y, B1.y)
                     + fmaxf(A0.z, B1.z) + fmaxf(A0.w, B1.w);
                s10 += fmaxf(A1.x, B0.x) + fmaxf(A1.y, B0.y)
                     + fmaxf(A1.z, B0.z) + fmaxf(A1.w, B0.w);
                s11 += fmaxf(A1.x, B1.x) + fmaxf(A1.y, B1.y)
                     + fmaxf(A1.z, B1.z) + fmaxf(A1.w, B1.w);
            }
            const float c = 1.0f / 64.0f;
            const float ksa = ksum_s[ka], ksb = ksum_s[kb];
            Tr[qa][ka] = 1.0f - (s00 - ksa) * c;
            Tr[qa][kb] = 1.0f - (s01 - ksb) * c;
            Tr[qb][ka] = 1.0f - (s10 - ksa) * c;
            Tr[qb][kb] = 1.0f - (s11 - ksb) * c;
        }
        __syncthreads();

        if (t < nq) {
            float r = 0.f;
#pragma unroll
            for (int k = 0; k < 32; k++) r += Tr[t][k];
            rs_s[t] += r;
        }

        if (qf_active) {
#pragma unroll
            for (int k = 0; k < 32; k++) {
                float tv = Tr[qf][k];
                float4 v0 = *(const float4*)&Vs_s[k][dg];
                float4 v1 = *(const float4*)&Vs_s[k][dg + 4];
                acc[0] = fmaf(tv, v0.x, acc[0]);
                acc[1] = fmaf(tv, v0.y, acc[1]);
                acc[2] = fmaf(tv, v0.z, acc[2]);
                acc[3] = fmaf(tv, v0.w, acc[3]);
                acc[4] = fmaf(tv, v1.x, acc[4]);
                acc[5] = fmaf(tv, v1.y, acc[5]);
                acc[6] = fmaf(tv, v1.z, acc[6]);
                acc[7] = fmaf(tv, v1.w, acc[7]);
            }
        }
    }
    __syncthreads();

    // store split partials for active rows only
    if (qf_active) {
        float4 o0 = make_float4(acc[0], acc[1], acc[2], acc[3]);
        float4 o1 = make_float4(acc[4], acc[5], acc[6], acc[7]);
        const int s = sidx[qf];
        *(float4*)&g_pacc[z][s][h * DH_ + dg]     = o0;
        *(float4*)&g_pacc[z][s][h * DH_ + dg + 4] = o1;
    }
    if (t < nq) g_prs[z][sidx[t]][h] = rs_s[t];
}

// ---------------------------------------------------------------------------
// Combine splits + gate -> G
// ---------------------------------------------------------------------------
__global__ void __launch_bounds__(256)
k_norm() {
    const int s = blockIdx.x;
    const int t = threadIdx.x;
#pragma unroll
    for (int j = t; j < DM_; j += 256) {
        int h = j >> 6;
        float gate = g_gate[s][h];
        float v = 0.f;
        if (gate != 0.f) {
            float rs = 0.f, a = 0.f;
#pragma unroll
            for (int z = 0; z < NSPL; z++) {
                rs += g_prs[z][s][h];
                a  += g_pacc[z][s][j];
            }
            v = a * gate / (rs + 1e-9f);
        }
        g_G[s * DM_ + j] = v;
    }
}

// ---------------------------------------------------------------------------
extern "C" void kernel_launch(void* const* d_in, const int* in_sizes, int n_in,
                              void* d_out, int out_size) {
    const float* x  = (const float*)d_in[0];
    const float* fc = (const float*)d_in[1];
    const float* fs = (const float*)d_in[2];
    const float* Wq = (const float*)d_in[3];
    const float* Wk = (const float*)d_in[4];
    const float* Wv = (const float*)d_in[5];
    const float* Wo = (const float*)d_in[6];
    const float* Wr = (const float*)d_in[7];
    float* out = (float*)d_out;

    k_gemm_qkv<<<dim3(8, 8, 3), 256>>>(x, Wq, Wk, Wv);
    k_router  <<<S_, 256>>>(x, Wr);
    k_rope_sig<<<S_, 256>>>(fc, fs);
    k_compact <<<1, 256>>>();
    k_attn    <<<dim3(16, H_, NSPL), 256>>>();
    k_norm    <<<S_, 256>>>();
    k_gemm_out<<<dim3(8, 8), 256>>>(Wo, out);
}

// round 8
// speedup vs baseline: 1.2678x; 1.0890x over previous
#include <cuda_runtime.h>

// ---------------------------------------------------------------------------
// MultiUniverseToposAttention  B=1 S=512 H=8 DH=64 DM=512 TOP_K=2
//   1) k_gemm_qkv (z=0..2): Q,K,V = x @ sig(W)^T via 3xTF32 mma.sync
//      (block 0 also zeroes g_qcnt for the router's atomic compaction)
//   2) k_router: logits -> softmax -> top2 -> gates + atomic per-head
//      query compaction (order nondeterministic, output order-independent)
//   3) k_rope_sig: RoPE+sigmoid -> head-major Qs,Ks; V head-major; Ksum
//   4) k_attn (split-K x8, compacted): truth = 1-(sum max(q,k)-Ksum)/64
//   5) k_norm: combine splits + gate -> G
//   6) k_gemm_out: out = G @ sig(Wo)^T  (3xTF32)
// ---------------------------------------------------------------------------

#define S_    512
#define DM_   512
#define H_    8
#define DH_   64
#define HALF_ 32
#define NSPL  8
#define KPS   (S_ / NSPL)

__device__ float g_Q [S_ * DM_];
__device__ float g_K [S_ * DM_];
__device__ float g_V [S_ * DM_];
__device__ float g_Qs[H_][S_][DH_];
__device__ float g_Ks[H_][S_][DH_];
__device__ float g_Vh[H_][S_][DH_];
__device__ float g_Ksum[H_][S_];
__device__ float g_gate[S_][H_];
__device__ int   g_qidx[H_][S_];
__device__ int   g_qcnt[H_];
__device__ float g_G [S_ * DM_];
__device__ float g_pacc[NSPL][S_][DM_];
__device__ float g_prs [NSPL][S_][H_];

__device__ __forceinline__ float sigf(float x) {
    return 1.0f / (1.0f + __expf(-x));
}
__device__ __forceinline__ unsigned f2tf(float x) {
    unsigned u;
    asm("cvt.rna.tf32.f32 %0, %1;" : "=r"(u) : "f"(x));
    return u;
}
__device__ __forceinline__ void mma_tf32(float c[4], const unsigned a[4],
                                         const unsigned b[2]) {
    asm volatile(
        "mma.sync.aligned.m16n8k8.row.col.f32.tf32.tf32.f32 "
        "{%0,%1,%2,%3}, {%4,%5,%6,%7}, {%8,%9}, {%0,%1,%2,%3};"
        : "+f"(c[0]), "+f"(c[1]), "+f"(c[2]), "+f"(c[3])
        : "r"(a[0]), "r"(a[1]), "r"(a[2]), "r"(a[3]), "r"(b[0]), "r"(b[1]));
}

// ---------------------------------------------------------------------------
// 3xTF32 GEMM: C[m][n] = sum_k A[m][k]*sig(W[n][k]); M=N=K=512.
// Block tile 64x64, BK=32, 256 threads (8 warps 2m x 4n), warp tile 32x16.
// Canonical smem layout As/Bs[64][36] (pad 36 -> fragment LDS bank =
// (4*row+tg)%32, all 32 lanes distinct). hi/lo tf32 split in registers.
// ---------------------------------------------------------------------------
__device__ __forceinline__ void gemm_tf32_body(const float* __restrict__ A,
                                               const float* __restrict__ W,
                                               float* __restrict__ C) {
    __shared__ float As[64][36];
    __shared__ float Bs[64][36];

    const int t    = threadIdx.x;
    const int lane = t & 31, w = t >> 5;
    const int wm = w & 1, wn = w >> 1;          // 2 x 4 warp grid
    const int g  = lane >> 2, tg = lane & 3;    // mma group / thread-in-group
    const int m0 = blockIdx.y * 64, n0 = blockIdx.x * 64;

    const int rowL = t >> 2;                    // 0..63
    const int cL   = (t & 3) << 3;              // 0,8,16,24

    float4 pa0, pa1, pb0, pb1;
    {
        const float* Ar = A + (m0 + rowL) * DM_;
        const float* Wr = W + (n0 + rowL) * DM_;
        pa0 = *(const float4*)&Ar[cL];
        pa1 = *(const float4*)&Ar[cL + 4];
        pb0 = *(const float4*)&Wr[cL];
        pb1 = *(const float4*)&Wr[cL + 4];
    }

    float acc[2][2][4] = {};

    for (int ch = 0; ch < 16; ch++) {
        __syncthreads();                        // consumers of prev chunk done
        *(float4*)&As[rowL][cL]     = pa0;
        *(float4*)&As[rowL][cL + 4] = pa1;
        *(float4*)&Bs[rowL][cL] =
            make_float4(sigf(pb0.x), sigf(pb0.y), sigf(pb0.z), sigf(pb0.w));
        *(float4*)&Bs[rowL][cL + 4] =
            make_float4(sigf(pb1.x), sigf(pb1.y), sigf(pb1.z), sigf(pb1.w));
        __syncthreads();                        // chunk visible

        if (ch < 15) {                          // prefetch next (overlaps mma)
            const int k0 = (ch + 1) * 32;
            const float* Ar = A + (m0 + rowL) * DM_ + k0;
            const float* Wr = W + (n0 + rowL) * DM_ + k0;
            pa0 = *(const float4*)&Ar[cL];
            pa1 = *(const float4*)&Ar[cL + 4];
            pb0 = *(const float4*)&Wr[cL];
            pb1 = *(const float4*)&Wr[cL + 4];
        }

#pragma unroll
        for (int ks = 0; ks < 4; ks++) {
            const int kb = ks * 8;
            unsigned ah[2][4], al[2][4];
#pragma unroll
            for (int i = 0; i < 2; i++) {
                const int rm = wm * 32 + i * 16 + g;
                const float v0 = As[rm    ][kb + tg];
                const float v1 = As[rm + 8][kb + tg];
                const float v2 = As[rm    ][kb + tg + 4];
                const float v3 = As[rm + 8][kb + tg + 4];
                ah[i][0] = f2tf(v0); al[i][0] = f2tf(v0 - __uint_as_float(ah[i][0]));
                ah[i][1] = f2tf(v1); al[i][1] = f2tf(v1 - __uint_as_float(ah[i][1]));
                ah[i][2] = f2tf(v2); al[i][2] = f2tf(v2 - __uint_as_float(ah[i][2]));
                ah[i][3] = f2tf(v3); al[i][3] = f2tf(v3 - __uint_as_float(ah[i][3]));
            }
            unsigned bh[2][2], bl[2][2];
#pragma unroll
            for (int j = 0; j < 2; j++) {
                const int rn = wn * 16 + j * 8 + g;
                const float v0 = Bs[rn][kb + tg];
                const float v1 = Bs[rn][kb + tg + 4];
                bh[j][0] = f2tf(v0); bl[j][0] = f2tf(v0 - __uint_as_float(bh[j][0]));
                bh[j][1] = f2tf(v1); bl[j][1] = f2tf(v1 - __uint_as_float(bh[j][1]));
            }
#pragma unroll
            for (int i = 0; i < 2; i++)
#pragma unroll
                for (int j = 0; j < 2; j++) {
                    mma_tf32(acc[i][j], ah[i], bl[j]);
                    mma_tf32(acc[i][j], al[i], bh[j]);
                    mma_tf32(acc[i][j], ah[i], bh[j]);
                }
        }
    }

    // epilogue: c0,c1 -> (g, 2tg),(g,2tg+1); c2,c3 -> row+8
#pragma unroll
    for (int i = 0; i < 2; i++)
#pragma unroll
        for (int j = 0; j < 2; j++) {
            const int gm = m0 + wm * 32 + i * 16 + g;
            const int gn = n0 + wn * 16 + j * 8 + tg * 2;
            *(float2*)&C[gm * DM_ + gn]       = make_float2(acc[i][j][0], acc[i][j][1]);
            *(float2*)&C[(gm + 8) * DM_ + gn] = make_float2(acc[i][j][2], acc[i][j][3]);
        }
}

__global__ void __launch_bounds__(256)
k_gemm_qkv(const float* __restrict__ x,
           const float* __restrict__ Wq,
           const float* __restrict__ Wk,
           const float* __restrict__ Wv) {
    // zero compaction counters (stream-ordered before k_router)
    if (blockIdx.z == 0 && blockIdx.x == 0 && blockIdx.y == 0 &&
        threadIdx.x < H_)
        g_qcnt[threadIdx.x] = 0;
    const float* W;
    float* C;
    if (blockIdx.z == 0)      { W = Wq; C = g_Q; }
    else if (blockIdx.z == 1) { W = Wk; C = g_K; }
    else                      { W = Wv; C = g_V; }
    gemm_tf32_body(x, W, C);
}

__global__ void __launch_bounds__(256)
k_gemm_out(const float* __restrict__ Wo, float* __restrict__ out) {
    gemm_tf32_body(g_G, Wo, out);
}

// ---------------------------------------------------------------------------
// Router: block per token, warp h computes head-h logit; thread 0 does
// softmax/top2/gates + atomic compaction into per-head query lists.
// ---------------------------------------------------------------------------
__global__ void __launch_bounds__(256)
k_router(const float* __restrict__ x, const float* __restrict__ Wr) {
    const int s = blockIdx.x;
    const int t = threadIdx.x;
    const int h = t >> 5, lane = t & 31;

    const float* xs = x + s * DM_;
    const float* wr = Wr + h * DM_;
    float acc = 0.f;
    for (int d = lane; d < DM_; d += 32)
        acc += xs[d] * sigf(wr[d]);
#pragma unroll
    for (int o = 16; o > 0; o >>= 1)
        acc += __shfl_xor_sync(0xFFFFFFFFu, acc, o);

    __shared__ float lg[H_];
    if (lane == 0) lg[h] = acc;
    __syncthreads();

    if (t == 0) {
        float m = lg[0];
#pragma unroll
        for (int i = 1; i < H_; i++) m = fmaxf(m, lg[i]);
        float e[H_];
        float Z = 0.f;
#pragma unroll
        for (int i = 0; i < H_; i++) { e[i] = expf(lg[i] - m); Z += e[i]; }
        int i0 = 0;
#pragma unroll
        for (int i = 1; i < H_; i++) if (e[i] > e[i0]) i0 = i;
        int i1 = (i0 == 0) ? 1 : 0;
#pragma unroll
        for (int i = 0; i < H_; i++) if (i != i0 && e[i] > e[i1]) i1 = i;
        float p0 = e[i0] / Z, p1 = e[i1] / Z;
        float inv = 1.0f / (p0 + p1 + 1e-9f);
#pragma unroll
        for (int i = 0; i < H_; i++) g_gate[s][i] = 0.f;
        g_gate[s][i0] = p0 * inv;
        g_gate[s][i1] = p1 * inv;
        int sl0 = atomicAdd(&g_qcnt[i0], 1);
        g_qidx[i0][sl0] = s;
        int sl1 = atomicAdd(&g_qcnt[i1], 1);
        g_qidx[i1][sl1] = s;
    }
}

// ---------------------------------------------------------------------------
// RoPE + sigmoid + head-major transpose + Ksum
// ---------------------------------------------------------------------------
__global__ void __launch_bounds__(256)
k_rope_sig(const float* __restrict__ fc, const float* __restrict__ fs) {
    const int s = blockIdx.x;
    const int t = threadIdx.x;
    const int h = t >> 5, p = t & 31;

    const float c  = fc[s * HALF_ + p];
    const float sn = fs[s * HALF_ + p];
    const int base = s * DM_ + h * DH_ + 2 * p;

    float q0 = g_Q[base], q1 = g_Q[base + 1];
    float k0 = g_K[base], k1 = g_K[base + 1];
    float qr0 = q0 * c - q1 * sn, qr1 = q0 * sn + q1 * c;
    float kr0 = k0 * c - k1 * sn, kr1 = k0 * sn + k1 * c;
    float ks0 = sigf(kr0), ks1 = sigf(kr1);
    g_Qs[h][s][2 * p]     = sigf(qr0);
    g_Qs[h][s][2 * p + 1] = sigf(qr1);
    g_Ks[h][s][2 * p]     = ks0;
    g_Ks[h][s][2 * p + 1] = ks1;

    float v = ks0 + ks1;
#pragma unroll
    for (int o = 16; o > 0; o >>= 1)
        v += __shfl_xor_sync(0xFFFFFFFFu, v, o);
    if (p == 0) g_Ksum[h][s] = v;

#pragma unroll
    for (int j = t; j < DM_; j += 256) {
        int h2 = j >> 6, d = j & 63;
        g_Vh[h2][s][d] = g_V[s * DM_ + j];
    }
}

// ---------------------------------------------------------------------------
// Attention, compacted queries, split-K x NSPL.
// truth[q,k] = 1 - (sum_d max(Qs,Ks) - Ksum_k)/64
// ---------------------------------------------------------------------------
__global__ void __launch_bounds__(256)
k_attn() {
    const int h   = blockIdx.y;
    const int cnt = g_qcnt[h];
    const int q0  = blockIdx.x * 32;
    if (q0 >= cnt) return;
    const int nq  = min(32, cnt - q0);
    const int z   = blockIdx.z;
    const int t   = threadIdx.x;

    __shared__ float Qs_s[32][68];
    __shared__ float Ks_s[32][68];
    __shared__ float Vs_s[32][68];
    __shared__ float Tr  [32][33];
    __shared__ float rs_s[32];
    __shared__ float ksum_s[32];
    __shared__ int   sidx[32];

    if (t < 32) {
        int s = g_qidx[h][q0 + ((t < nq) ? t : 0)];
        sidx[t] = s;
        rs_s[t] = 0.f;
    }
    __syncthreads();

#pragma unroll
    for (int j = t; j < 32 * 16; j += 256) {
        int r = j >> 4, c4 = (j & 15) << 2;
        *(float4*)&Qs_s[r][c4] = *(const float4*)&g_Qs[h][sidx[r]][c4];
    }

    const int qq = t >> 4, kk = t & 15;
    const int qa = 2 * qq, qb = qa + 1;
    const int ka = 2 * kk, kb = ka + 1;

    const int qf = t >> 3;
    const int dg = (t & 7) << 3;
    float acc[8] = {};
    const bool qf_active = (qf < nq);

    for (int kt = 0; kt < KPS / 32; kt++) {
        const int k0 = z * KPS + kt * 32;
        __syncthreads();
#pragma unroll
        for (int j = t; j < 32 * 16; j += 256) {
            int r = j >> 4, c4 = (j & 15) << 2;
            *(float4*)&Ks_s[r][c4] = *(const float4*)&g_Ks[h][k0 + r][c4];
            *(float4*)&Vs_s[r][c4] = *(const float4*)&g_Vh[h][k0 + r][c4];
        }
        if (t < 32) ksum_s[t] = g_Ksum[h][k0 + t];
        __syncthreads();

        {
            float s00 = 0.f, s01 = 0.f, s10 = 0.f, s11 = 0.f;
#pragma unroll
            for (int d = 0; d < 64; d += 4) {
                float4 A0 = *(const float4*)&Qs_s[qa][d];
                float4 A1 = *(const float4*)&Qs_s[qb][d];
                float4 B0 = *(const float4*)&Ks_s[ka][d];
                float4 B1 = *(const float4*)&Ks_s[kb][d];
                s00 += fmaxf(A0.x, B0.x) + fmaxf(A0.y, B0.y)
                     + fmaxf(A0.z, B0.z) + fmaxf(A0.w, B0.w);
                s01 += fmaxf(A0.x, B1.x) + fmaxf(A0.y, B1.y)
                     + fmaxf(A0.z, B1.z) + fmaxf(A0.w, B1.w);
                s10 += fmaxf(A1.x, B0.x) + fmaxf(A1.y, B0.y)
                     + fmaxf(A1.z, B0.z) + fmaxf(A1.w, B0.w);
                s11 += fmaxf(A1.x, B1.x) + fmaxf(A1.y, B1.y)
                     + fmaxf(A1.z, B1.z) + fmaxf(A1.w, B1.w);
            }
            const float c = 1.0f / 64.0f;
            const float ksa = ksum_s[ka], ksb = ksum_s[kb];
            Tr[qa][ka] = 1.0f - (s00 - ksa) * c;
            Tr[qa][kb] = 1.0f - (s01 - ksb) * c;
            Tr[qb][ka] = 1.0f - (s10 - ksa) * c;
            Tr[qb][kb] = 1.0f - (s11 - ksb) * c;
        }
        __syncthreads();

        if (t < nq) {
            float r = 0.f;
#pragma unroll
            for (int k = 0; k < 32; k++) r += Tr[t][k];
            rs_s[t] += r;
        }

        if (qf_active) {
#pragma unroll
            for (int k = 0; k < 32; k++) {
                float tv = Tr[qf][k];
                float4 v0 = *(const float4*)&Vs_s[k][dg];
                float4 v1 = *(const float4*)&Vs_s[k][dg + 4];
                acc[0] = fmaf(tv, v0.x, acc[0]);
                acc[1] = fmaf(tv, v0.y, acc[1]);
                acc[2] = fmaf(tv, v0.z, acc[2]);
                acc[3] = fmaf(tv, v0.w, acc[3]);
                acc[4] = fmaf(tv, v1.x, acc[4]);
                acc[5] = fmaf(tv, v1.y, acc[5]);
                acc[6] = fmaf(tv, v1.z, acc[6]);
                acc[7] = fmaf(tv, v1.w, acc[7]);
            }
        }
    }
    __syncthreads();

    if (qf_active) {
        const int s = sidx[qf];
        *(float4*)&g_pacc[z][s][h * DH_ + dg] =
            make_float4(acc[0], acc[1], acc[2], acc[3]);
        *(float4*)&g_pacc[z][s][h * DH_ + dg + 4] =
            make_float4(acc[4], acc[5], acc[6], acc[7]);
    }
    if (t < nq) g_prs[z][sidx[t]][h] = rs_s[t];
}

// ---------------------------------------------------------------------------
// Combine splits + gate -> G
// ---------------------------------------------------------------------------
__global__ void __launch_bounds__(256)
k_norm() {
    const int s = blockIdx.x;
    const int t = threadIdx.x;
#pragma unroll
    for (int j = t; j < DM_; j += 256) {
        int h = j >> 6;
        float gate = g_gate[s][h];
        float v = 0.f;
        if (gate != 0.f) {
            float rs = 0.f, a = 0.f;
#pragma unroll
            for (int z = 0; z < NSPL; z++) {
                rs += g_prs[z][s][h];
                a  += g_pacc[z][s][j];
            }
            v = a * gate / (rs + 1e-9f);
        }
        g_G[s * DM_ + j] = v;
    }
}

// ---------------------------------------------------------------------------
extern "C" void kernel_launch(void* const* d_in, const int* in_sizes, int n_in,
                              void* d_out, int out_size) {
    const float* x  = (const float*)d_in[0];
    const float* fc = (const float*)d_in[1];
    const float* fs = (const float*)d_in[2];
    const float* Wq = (const float*)d_in[3];
    const float* Wk = (const float*)d_in[4];
    const float* Wv = (const float*)d_in[5];
    const float* Wo = (const float*)d_in[6];
    const float* Wr = (const float*)d_in[7];
    float* out = (float*)d_out;

    k_gemm_qkv<<<dim3(8, 8, 3), 256>>>(x, Wq, Wk, Wv);
    k_router  <<<S_, 256>>>(x, Wr);
    k_rope_sig<<<S_, 256>>>(fc, fs);
    k_attn    <<<dim3(16, H_, NSPL), 256>>>();
    k_norm    <<<S_, 256>>>();
    k_gemm_out<<<dim3(8, 8), 256>>>(Wo, out);
}

// round 9
// speedup vs baseline: 1.2681x; 1.0003x over previous
#include <cuda_runtime.h>

// ---------------------------------------------------------------------------
// MultiUniverseToposAttention  B=1 S=512 H=8 DH=64 DM=512 TOP_K=2
//   1) k_gemm_qkv (z=0..2): Q,K,V = x @ sig(W)^T via 3xTF32 mma.sync
//      (block 0 also zeroes g_qcnt for the router's atomic compaction)
//   2) k_router: logits -> softmax -> top2 -> gates + atomic per-head
//      query compaction (order nondeterministic, output order-independent)
//   3) k_rope_sig: RoPE+sigmoid -> head-major Qs,Ks; V head-major; Ksum
//   4) k_attn (split-K x8, compacted): truth = 1-(sum max(q,k)-Ksum)/64
//   5) k_norm: combine splits + gate -> G
//   6) k_gemm_out: out = G @ sig(Wo)^T  (3xTF32)
// ---------------------------------------------------------------------------

#define S_    512
#define DM_   512
#define H_    8
#define DH_   64
#define HALF_ 32
#define NSPL  8
#define KPS   (S_ / NSPL)

__device__ float g_Q [S_ * DM_];
__device__ float g_K [S_ * DM_];
__device__ float g_V [S_ * DM_];
__device__ float g_Qs[H_][S_][DH_];
__device__ float g_Ks[H_][S_][DH_];
__device__ float g_Vh[H_][S_][DH_];
__device__ float g_Ksum[H_][S_];
__device__ float g_gate[S_][H_];
__device__ int   g_qidx[H_][S_];
__device__ int   g_qcnt[H_];
__device__ float g_G [S_ * DM_];
__device__ float g_pacc[NSPL][S_][DM_];
__device__ float g_prs [NSPL][S_][H_];

__device__ __forceinline__ float sigf(float x) {
    return 1.0f / (1.0f + __expf(-x));
}
__device__ __forceinline__ unsigned f2tf(float x) {
    unsigned u;
    asm("cvt.rna.tf32.f32 %0, %1;" : "=r"(u) : "f"(x));
    return u;
}
__device__ __forceinline__ void mma_tf32(float c[4], const unsigned a[4],
                                         const unsigned b[2]) {
    asm volatile(
        "mma.sync.aligned.m16n8k8.row.col.f32.tf32.tf32.f32 "
        "{%0,%1,%2,%3}, {%4,%5,%6,%7}, {%8,%9}, {%0,%1,%2,%3};"
        : "+f"(c[0]), "+f"(c[1]), "+f"(c[2]), "+f"(c[3])
        : "r"(a[0]), "r"(a[1]), "r"(a[2]), "r"(a[3]), "r"(b[0]), "r"(b[1]));
}

// ---------------------------------------------------------------------------
// 3xTF32 GEMM: C[m][n] = sum_k A[m][k]*sig(W[n][k]); M=N=K=512.
// Block tile 64x64, BK=32, 256 threads (8 warps 2m x 4n), warp tile 32x16.
// Canonical smem layout As/Bs[64][36] (pad 36 -> fragment LDS bank =
// (4*row+tg)%32, all 32 lanes distinct). hi/lo tf32 split in registers.
// ---------------------------------------------------------------------------
__device__ __forceinline__ void gemm_tf32_body(const float* __restrict__ A,
                                               const float* __restrict__ W,
                                               float* __restrict__ C) {
    __shared__ float As[64][36];
    __shared__ float Bs[64][36];

    const int t    = threadIdx.x;
    const int lane = t & 31, w = t >> 5;
    const int wm = w & 1, wn = w >> 1;          // 2 x 4 warp grid
    const int g  = lane >> 2, tg = lane & 3;    // mma group / thread-in-group
    const int m0 = blockIdx.y * 64, n0 = blockIdx.x * 64;

    const int rowL = t >> 2;                    // 0..63
    const int cL   = (t & 3) << 3;              // 0,8,16,24

    float4 pa0, pa1, pb0, pb1;
    {
        const float* Ar = A + (m0 + rowL) * DM_;
        const float* Wr = W + (n0 + rowL) * DM_;
        pa0 = *(const float4*)&Ar[cL];
        pa1 = *(const float4*)&Ar[cL + 4];
        pb0 = *(const float4*)&Wr[cL];
        pb1 = *(const float4*)&Wr[cL + 4];
    }

    float acc[2][2][4] = {};

    for (int ch = 0; ch < 16; ch++) {
        __syncthreads();                        // consumers of prev chunk done
        *(float4*)&As[rowL][cL]     = pa0;
        *(float4*)&As[rowL][cL + 4] = pa1;
        *(float4*)&Bs[rowL][cL] =
            make_float4(sigf(pb0.x), sigf(pb0.y), sigf(pb0.z), sigf(pb0.w));
        *(float4*)&Bs[rowL][cL + 4] =
            make_float4(sigf(pb1.x), sigf(pb1.y), sigf(pb1.z), sigf(pb1.w));
        __syncthreads();                        // chunk visible

        if (ch < 15) {                          // prefetch next (overlaps mma)
            const int k0 = (ch + 1) * 32;
            const float* Ar = A + (m0 + rowL) * DM_ + k0;
            const float* Wr = W + (n0 + rowL) * DM_ + k0;
            pa0 = *(const float4*)&Ar[cL];
            pa1 = *(const float4*)&Ar[cL + 4];
            pb0 = *(const float4*)&Wr[cL];
            pb1 = *(const float4*)&Wr[cL + 4];
        }

#pragma unroll
        for (int ks = 0; ks < 4; ks++) {
            const int kb = ks * 8;
            unsigned ah[2][4], al[2][4];
#pragma unroll
            for (int i = 0; i < 2; i++) {
                const int rm = wm * 32 + i * 16 + g;
                const float v0 = As[rm    ][kb + tg];
                const float v1 = As[rm + 8][kb + tg];
                const float v2 = As[rm    ][kb + tg + 4];
                const float v3 = As[rm + 8][kb + tg + 4];
                ah[i][0] = f2tf(v0); al[i][0] = f2tf(v0 - __uint_as_float(ah[i][0]));
                ah[i][1] = f2tf(v1); al[i][1] = f2tf(v1 - __uint_as_float(ah[i][1]));
                ah[i][2] = f2tf(v2); al[i][2] = f2tf(v2 - __uint_as_float(ah[i][2]));
                ah[i][3] = f2tf(v3); al[i][3] = f2tf(v3 - __uint_as_float(ah[i][3]));
            }
            unsigned bh[2][2], bl[2][2];
#pragma unroll
            for (int j = 0; j < 2; j++) {
                const int rn = wn * 16 + j * 8 + g;
                const float v0 = Bs[rn][kb + tg];
                const float v1 = Bs[rn][kb + tg + 4];
                bh[j][0] = f2tf(v0); bl[j][0] = f2tf(v0 - __uint_as_float(bh[j][0]));
                bh[j][1] = f2tf(v1); bl[j][1] = f2tf(v1 - __uint_as_float(bh[j][1]));
            }
#pragma unroll
            for (int i = 0; i < 2; i++)
#pragma unroll
                for (int j = 0; j < 2; j++) {
                    mma_tf32(acc[i][j], ah[i], bl[j]);
                    mma_tf32(acc[i][j], al[i], bh[j]);
                    mma_tf32(acc[i][j], ah[i], bh[j]);
                }
        }
    }

    // epilogue: c0,c1 -> (g, 2tg),(g,2tg+1); c2,c3 -> row+8
#pragma unroll
    for (int i = 0; i < 2; i++)
#pragma unroll
        for (int j = 0; j < 2; j++) {
            const int gm = m0 + wm * 32 + i * 16 + g;
            const int gn = n0 + wn * 16 + j * 8 + tg * 2;
            *(float2*)&C[gm * DM_ + gn]       = make_float2(acc[i][j][0], acc[i][j][1]);
            *(float2*)&C[(gm + 8) * DM_ + gn] = make_float2(acc[i][j][2], acc[i][j][3]);
        }
}

__global__ void __launch_bounds__(256)
k_gemm_qkv(const float* __restrict__ x,
           const float* __restrict__ Wq,
           const float* __restrict__ Wk,
           const float* __restrict__ Wv) {
    // zero compaction counters (stream-ordered before k_router)
    if (blockIdx.z == 0 && blockIdx.x == 0 && blockIdx.y == 0 &&
        threadIdx.x < H_)
        g_qcnt[threadIdx.x] = 0;
    const float* W;
    float* C;
    if (blockIdx.z == 0)      { W = Wq; C = g_Q; }
    else if (blockIdx.z == 1) { W = Wk; C = g_K; }
    else                      { W = Wv; C = g_V; }
    gemm_tf32_body(x, W, C);
}

__global__ void __launch_bounds__(256)
k_gemm_out(const float* __restrict__ Wo, float* __restrict__ out) {
    gemm_tf32_body(g_G, Wo, out);
}

// ---------------------------------------------------------------------------
// Router: block per token, warp h computes head-h logit; thread 0 does
// softmax/top2/gates + atomic compaction into per-head query lists.
// ---------------------------------------------------------------------------
__global__ void __launch_bounds__(256)
k_router(const float* __restrict__ x, const float* __restrict__ Wr) {
    const int s = blockIdx.x;
    const int t = threadIdx.x;
    const int h = t >> 5, lane = t & 31;

    const float* xs = x + s * DM_;
    const float* wr = Wr + h * DM_;
    float acc = 0.f;
    for (int d = lane; d < DM_; d += 32)
        acc += xs[d] * sigf(wr[d]);
#pragma unroll
    for (int o = 16; o > 0; o >>= 1)
        acc += __shfl_xor_sync(0xFFFFFFFFu, acc, o);

    __shared__ float lg[H_];
    if (lane == 0) lg[h] = acc;
    __syncthreads();

    if (t == 0) {
        float m = lg[0];
#pragma unroll
        for (int i = 1; i < H_; i++) m = fmaxf(m, lg[i]);
        float e[H_];
        float Z = 0.f;
#pragma unroll
        for (int i = 0; i < H_; i++) { e[i] = expf(lg[i] - m); Z += e[i]; }
        int i0 = 0;
#pragma unroll
        for (int i = 1; i < H_; i++) if (e[i] > e[i0]) i0 = i;
        int i1 = (i0 == 0) ? 1 : 0;
#pragma unroll
        for (int i = 0; i < H_; i++) if (i != i0 && e[i] > e[i1]) i1 = i;
        float p0 = e[i0] / Z, p1 = e[i1] / Z;
        float inv = 1.0f / (p0 + p1 + 1e-9f);
#pragma unroll
        for (int i = 0; i < H_; i++) g_gate[s][i] = 0.f;
        g_gate[s][i0] = p0 * inv;
        g_gate[s][i1] = p1 * inv;
        int sl0 = atomicAdd(&g_qcnt[i0], 1);
        g_qidx[i0][sl0] = s;
        int sl1 = atomicAdd(&g_qcnt[i1], 1);
        g_qidx[i1][sl1] = s;
    }
}

// ---------------------------------------------------------------------------
// RoPE + sigmoid + head-major transpose + Ksum
// ---------------------------------------------------------------------------
__global__ void __launch_bounds__(256)
k_rope_sig(const float* __restrict__ fc, const float* __restrict__ fs) {
    const int s = blockIdx.x;
    const int t = threadIdx.x;
    const int h = t >> 5, p = t & 31;

    const float c  = fc[s * HALF_ + p];
    const float sn = fs[s * HALF_ + p];
    const int base = s * DM_ + h * DH_ + 2 * p;

    float q0 = g_Q[base], q1 = g_Q[base + 1];
    float k0 = g_K[base], k1 = g_K[base + 1];
    float qr0 = q0 * c - q1 * sn, qr1 = q0 * sn + q1 * c;
    float kr0 = k0 * c - k1 * sn, kr1 = k0 * sn + k1 * c;
    float ks0 = sigf(kr0), ks1 = sigf(kr1);
    g_Qs[h][s][2 * p]     = sigf(qr0);
    g_Qs[h][s][2 * p + 1] = sigf(qr1);
    g_Ks[h][s][2 * p]     = ks0;
    g_Ks[h][s][2 * p + 1] = ks1;

    float v = ks0 + ks1;
#pragma unroll
    for (int o = 16; o > 0; o >>= 1)
        v += __shfl_xor_sync(0xFFFFFFFFu, v, o);
    if (p == 0) g_Ksum[h][s] = v;

#pragma unroll
    for (int j = t; j < DM_; j += 256) {
        int h2 = j >> 6, d = j & 63;
        g_Vh[h2][s][d] = g_V[s * DM_ + j];
    }
}

// ---------------------------------------------------------------------------
// Attention, compacted queries, split-K x NSPL.
// truth[q,k] = 1 - (sum_d max(Qs,Ks) - Ksum_k)/64
// ---------------------------------------------------------------------------
__global__ void __launch_bounds__(256)
k_attn() {
    const int h   = blockIdx.y;
    const int cnt = g_qcnt[h];
    const int q0  = blockIdx.x * 32;
    if (q0 >= cnt) return;
    const int nq  = min(32, cnt - q0);
    const int z   = blockIdx.z;
    const int t   = threadIdx.x;

    __shared__ float Qs_s[32][68];
    __shared__ float Ks_s[32][68];
    __shared__ float Vs_s[32][68];
    __shared__ float Tr  [32][33];
    __shared__ float rs_s[32];
    __shared__ float ksum_s[32];
    __shared__ int   sidx[32];

    if (t < 32) {
        int s = g_qidx[h][q0 + ((t < nq) ? t : 0)];
        sidx[t] = s;
        rs_s[t] = 0.f;
    }
    __syncthreads();

#pragma unroll
    for (int j = t; j < 32 * 16; j += 256) {
        int r = j >> 4, c4 = (j & 15) << 2;
        *(float4*)&Qs_s[r][c4] = *(const float4*)&g_Qs[h][sidx[r]][c4];
    }

    const int qq = t >> 4, kk = t & 15;
    const int qa = 2 * qq, qb = qa + 1;
    const int ka = 2 * kk, kb = ka + 1;

    const int qf = t >> 3;
    const int dg = (t & 7) << 3;
    float acc[8] = {};
    const bool qf_active = (qf < nq);

    for (int kt = 0; kt < KPS / 32; kt++) {
        const int k0 = z * KPS + kt * 32;
        __syncthreads();
#pragma unroll
        for (int j = t; j < 32 * 16; j += 256) {
            int r = j >> 4, c4 = (j & 15) << 2;
            *(float4*)&Ks_s[r][c4] = *(const float4*)&g_Ks[h][k0 + r][c4];
            *(float4*)&Vs_s[r][c4] = *(const float4*)&g_Vh[h][k0 + r][c4];
        }
        if (t < 32) ksum_s[t] = g_Ksum[h][k0 + t];
        __syncthreads();

        {
            float s00 = 0.f, s01 = 0.f, s10 = 0.f, s11 = 0.f;
#pragma unroll
            for (int d = 0; d < 64; d += 4) {
                float4 A0 = *(const float4*)&Qs_s[qa][d];
                float4 A1 = *(const float4*)&Qs_s[qb][d];
                float4 B0 = *(const float4*)&Ks_s[ka][d];
                float4 B1 = *(const float4*)&Ks_s[kb][d];
                s00 += fmaxf(A0.x, B0.x) + fmaxf(A0.y, B0.y)
                     + fmaxf(A0.z, B0.z) + fmaxf(A0.w, B0.w);
                s01 += fmaxf(A0.x, B1.x) + fmaxf(A0.y, B1.y)
                     + fmaxf(A0.z, B1.z) + fmaxf(A0.w, B1.w);
                s10 += fmaxf(A1.x, B0.x) + fmaxf(A1.y, B0.y)
                     + fmaxf(A1.z, B0.z) + fmaxf(A1.w, B0.w);
                s11 += fmaxf(A1.x, B1.x) + fmaxf(A1.y, B1.y)
                     + fmaxf(A1.z, B1.z) + fmaxf(A1.w, B1.w);
            }
            const float c = 1.0f / 64.0f;
            const float ksa = ksum_s[ka], ksb = ksum_s[kb];
            Tr[qa][ka] = 1.0f - (s00 - ksa) * c;
            Tr[qa][kb] = 1.0f - (s01 - ksb) * c;
            Tr[qb][ka] = 1.0f - (s10 - ksa) * c;
            Tr[qb][kb] = 1.0f - (s11 - ksb) * c;
        }
        __syncthreads();

        if (t < nq) {
            float r = 0.f;
#pragma unroll
            for (int k = 0; k < 32; k++) r += Tr[t][k];
            rs_s[t] += r;
        }

        if (qf_active) {
#pragma unroll
            for (int k = 0; k < 32; k++) {
                float tv = Tr[qf][k];
                float4 v0 = *(const float4*)&Vs_s[k][dg];
                float4 v1 = *(const float4*)&Vs_s[k][dg + 4];
                acc[0] = fmaf(tv, v0.x, acc[0]);
                acc[1] = fmaf(tv, v0.y, acc[1]);
                acc[2] = fmaf(tv, v0.z, acc[2]);
                acc[3] = fmaf(tv, v0.w, acc[3]);
                acc[4] = fmaf(tv, v1.x, acc[4]);
                acc[5] = fmaf(tv, v1.y, acc[5]);
                acc[6] = fmaf(tv, v1.z, acc[6]);
                acc[7] = fmaf(tv, v1.w, acc[7]);
            }
        }
    }
    __syncthreads();

    if (qf_active) {
        const int s = sidx[qf];
        *(float4*)&g_pacc[z][s][h * DH_ + dg] =
            make_float4(acc[0], acc[1], acc[2], acc[3]);
        *(float4*)&g_pacc[z][s][h * DH_ + dg + 4] =
            make_float4(acc[4], acc[5], acc[6], acc[7]);
    }
    if (t < nq) g_prs[z][sidx[t]][h] = rs_s[t];
}

// ---------------------------------------------------------------------------
// Combine splits + gate -> G
// ---------------------------------------------------------------------------
__global__ void __launch_bounds__(256)
k_norm() {
    const int s = blockIdx.x;
    const int t = threadIdx.x;
#pragma unroll
    for (int j = t; j < DM_; j += 256) {
        int h = j >> 6;
        float gate = g_gate[s][h];
        float v = 0.f;
        if (gate != 0.f) {
            float rs = 0.f, a = 0.f;
#pragma unroll
            for (int z = 0; z < NSPL; z++) {
                rs += g_prs[z][s][h];
                a  += g_pacc[z][s][j];
            }
            v = a * gate / (rs + 1e-9f);
        }
        g_G[s * DM_ + j] = v;
    }
}

// ---------------------------------------------------------------------------
extern "C" void kernel_launch(void* const* d_in, const int* in_sizes, int n_in,
                              void* d_out, int out_size) {
    const float* x  = (const float*)d_in[0];
    const float* fc = (const float*)d_in[1];
    const float* fs = (const float*)d_in[2];
    const float* Wq = (const float*)d_in[3];
    const float* Wk = (const float*)d_in[4];
    const float* Wv = (const float*)d_in[5];
    const float* Wo = (const float*)d_in[6];
    const float* Wr = (const float*)d_in[7];
    float* out = (float*)d_out;

    k_gemm_qkv<<<dim3(8, 8, 3), 256>>>(x, Wq, Wk, Wv);
    k_router  <<<S_, 256>>>(x, Wr);
    k_rope_sig<<<S_, 256>>>(fc, fs);
    k_attn    <<<dim3(16, H_, NSPL), 256>>>();
    k_norm    <<<S_, 256>>>();
    k_gemm_out<<<dim3(8, 8), 256>>>(Wo, out);
}

// round 10
// speedup vs baseline: 1.3113x; 1.0340x over previous
#include <cuda_runtime.h>

// ---------------------------------------------------------------------------
// MultiUniverseToposAttention  B=1 S=512 H=8 DH=64 DM=512 TOP_K=2
//   1) k_gemm_qkv (z=0..2): Q,K,V = x @ sig(W)^T via 3xTF32 mma.sync
//      (z=3): router gates (logits -> softmax -> top2), reads x only
//   2) k_rope_sig (grid 520): blocks 0..511 RoPE+sigmoid -> head-major
//      Qs,Ks,Vh + Ksum; blocks 512..519 per-head ballot-scan compaction
//   3) k_attn (128 thr, 16-q tiles, split-K x8): truth = 1-(summax-Ksum)/64
//   4) k_norm: combine splits + gate -> G
//   5) k_gemm_out: out = G @ sig(Wo)^T  (3xTF32)
// ---------------------------------------------------------------------------

#define S_    512
#define DM_   512
#define H_    8
#define DH_   64
#define HALF_ 32
#define NSPL  8
#define KPS   (S_ / NSPL)
#define QT    16

__device__ float g_Q [S_ * DM_];
__device__ float g_K [S_ * DM_];
__device__ float g_V [S_ * DM_];
__device__ float g_Qs[H_][S_][DH_];
__device__ float g_Ks[H_][S_][DH_];
__device__ float g_Vh[H_][S_][DH_];
__device__ float g_Ksum[H_][S_];
__device__ float g_gate[S_][H_];
__device__ int   g_qidx[H_][S_];
__device__ int   g_qcnt[H_];
__device__ float g_G [S_ * DM_];
__device__ float g_pacc[NSPL][S_][DM_];
__device__ float g_prs [NSPL][S_][H_];

__device__ __forceinline__ float sigf(float x) {
    return 1.0f / (1.0f + __expf(-x));
}
__device__ __forceinline__ unsigned f2tf(float x) {
    unsigned u;
    asm("cvt.rna.tf32.f32 %0, %1;" : "=r"(u) : "f"(x));
    return u;
}
__device__ __forceinline__ void mma_tf32(float c[4], const unsigned a[4],
                                         const unsigned b[2]) {
    asm volatile(
        "mma.sync.aligned.m16n8k8.row.col.f32.tf32.tf32.f32 "
        "{%0,%1,%2,%3}, {%4,%5,%6,%7}, {%8,%9}, {%0,%1,%2,%3};"
        : "+f"(c[0]), "+f"(c[1]), "+f"(c[2]), "+f"(c[3])
        : "r"(a[0]), "r"(a[1]), "r"(a[2]), "r"(a[3]), "r"(b[0]), "r"(b[1]));
}

// ---------------------------------------------------------------------------
// 3xTF32 GEMM (validated R9): C = A @ sig(W)^T; 64x64 tile, BK=32, 256 thr.
// ---------------------------------------------------------------------------
__device__ __forceinline__ void gemm_tf32_body(const float* __restrict__ A,
                                               const float* __restrict__ W,
                                               float* __restrict__ C) {
    __shared__ float As[64][36];
    __shared__ float Bs[64][36];

    const int t    = threadIdx.x;
    const int lane = t & 31, w = t >> 5;
    const int wm = w & 1, wn = w >> 1;
    const int g  = lane >> 2, tg = lane & 3;
    const int m0 = blockIdx.y * 64, n0 = blockIdx.x * 64;

    const int rowL = t >> 2;
    const int cL   = (t & 3) << 3;

    float4 pa0, pa1, pb0, pb1;
    {
        const float* Ar = A + (m0 + rowL) * DM_;
        const float* Wr = W + (n0 + rowL) * DM_;
        pa0 = *(const float4*)&Ar[cL];
        pa1 = *(const float4*)&Ar[cL + 4];
        pb0 = *(const float4*)&Wr[cL];
        pb1 = *(const float4*)&Wr[cL + 4];
    }

    float acc[2][2][4] = {};

    for (int ch = 0; ch < 16; ch++) {
        __syncthreads();
        *(float4*)&As[rowL][cL]     = pa0;
        *(float4*)&As[rowL][cL + 4] = pa1;
        *(float4*)&Bs[rowL][cL] =
            make_float4(sigf(pb0.x), sigf(pb0.y), sigf(pb0.z), sigf(pb0.w));
        *(float4*)&Bs[rowL][cL + 4] =
            make_float4(sigf(pb1.x), sigf(pb1.y), sigf(pb1.z), sigf(pb1.w));
        __syncthreads();

        if (ch < 15) {
            const int k0 = (ch + 1) * 32;
            const float* Ar = A + (m0 + rowL) * DM_ + k0;
            const float* Wr = W + (n0 + rowL) * DM_ + k0;
            pa0 = *(const float4*)&Ar[cL];
            pa1 = *(const float4*)&Ar[cL + 4];
            pb0 = *(const float4*)&Wr[cL];
            pb1 = *(const float4*)&Wr[cL + 4];
        }

#pragma unroll
        for (int ks = 0; ks < 4; ks++) {
            const int kb = ks * 8;
            unsigned ah[2][4], al[2][4];
#pragma unroll
            for (int i = 0; i < 2; i++) {
                const int rm = wm * 32 + i * 16 + g;
                const float v0 = As[rm    ][kb + tg];
                const float v1 = As[rm + 8][kb + tg];
                const float v2 = As[rm    ][kb + tg + 4];
                const float v3 = As[rm + 8][kb + tg + 4];
                ah[i][0] = f2tf(v0); al[i][0] = f2tf(v0 - __uint_as_float(ah[i][0]));
                ah[i][1] = f2tf(v1); al[i][1] = f2tf(v1 - __uint_as_float(ah[i][1]));
                ah[i][2] = f2tf(v2); al[i][2] = f2tf(v2 - __uint_as_float(ah[i][2]));
                ah[i][3] = f2tf(v3); al[i][3] = f2tf(v3 - __uint_as_float(ah[i][3]));
            }
            unsigned bh[2][2], bl[2][2];
#pragma unroll
            for (int j = 0; j < 2; j++) {
                const int rn = wn * 16 + j * 8 + g;
                const float v0 = Bs[rn][kb + tg];
                const float v1 = Bs[rn][kb + tg + 4];
                bh[j][0] = f2tf(v0); bl[j][0] = f2tf(v0 - __uint_as_float(bh[j][0]));
                bh[j][1] = f2tf(v1); bl[j][1] = f2tf(v1 - __uint_as_float(bh[j][1]));
            }
#pragma unroll
            for (int i = 0; i < 2; i++)
#pragma unroll
                for (int j = 0; j < 2; j++) {
                    mma_tf32(acc[i][j], ah[i], bl[j]);
                    mma_tf32(acc[i][j], al[i], bh[j]);
                    mma_tf32(acc[i][j], ah[i], bh[j]);
                }
        }
    }

#pragma unroll
    for (int i = 0; i < 2; i++)
#pragma unroll
        for (int j = 0; j < 2; j++) {
            const int gm = m0 + wm * 32 + i * 16 + g;
            const int gn = n0 + wn * 16 + j * 8 + tg * 2;
            *(float2*)&C[gm * DM_ + gn]       = make_float2(acc[i][j][0], acc[i][j][1]);
            *(float2*)&C[(gm + 8) * DM_ + gn] = make_float2(acc[i][j][2], acc[i][j][3]);
        }
}

// ---------------------------------------------------------------------------
// Router body (z=3): 64 blocks x 8 warps = 512 tokens; warp per token.
// Gates only (compaction happens in k_rope_sig tail blocks).
// ---------------------------------------------------------------------------
__device__ __forceinline__ void router_body(const float* __restrict__ x,
                                            const float* __restrict__ Wr) {
    const int t = threadIdx.x;
    const int lane = t & 31, w = t >> 5;
    const int s = (blockIdx.y * 8 + blockIdx.x) * 8 + w;

    const float* xs = x + s * DM_;
    float acc[H_] = {};
#pragma unroll 4
    for (int ds = 0; ds < 16; ds++) {
        const int d = lane + 32 * ds;
        const float xv = xs[d];
#pragma unroll
        for (int h = 0; h < H_; h++)
            acc[h] = fmaf(xv, sigf(Wr[h * DM_ + d]), acc[h]);
    }
#pragma unroll
    for (int h = 0; h < H_; h++)
#pragma unroll
        for (int o = 16; o > 0; o >>= 1)
            acc[h] += __shfl_xor_sync(0xFFFFFFFFu, acc[h], o);

    if (lane == 0) {
        float m = acc[0];
#pragma unroll
        for (int i = 1; i < H_; i++) m = fmaxf(m, acc[i]);
        float e[H_];
        float Z = 0.f;
#pragma unroll
        for (int i = 0; i < H_; i++) { e[i] = expf(acc[i] - m); Z += e[i]; }
        int i0 = 0;
#pragma unroll
        for (int i = 1; i < H_; i++) if (e[i] > e[i0]) i0 = i;
        int i1 = (i0 == 0) ? 1 : 0;
#pragma unroll
        for (int i = 0; i < H_; i++) if (i != i0 && e[i] > e[i1]) i1 = i;
        float p0 = e[i0] / Z, p1 = e[i1] / Z;
        float inv = 1.0f / (p0 + p1 + 1e-9f);
#pragma unroll
        for (int i = 0; i < H_; i++) g_gate[s][i] = 0.f;
        g_gate[s][i0] = p0 * inv;
        g_gate[s][i1] = p1 * inv;
    }
}

__global__ void __launch_bounds__(256)
k_gemm_qkv(const float* __restrict__ x,
           const float* __restrict__ Wq,
           const float* __restrict__ Wk,
           const float* __restrict__ Wv,
           const float* __restrict__ Wr) {
    if (blockIdx.z == 3) { router_body(x, Wr); return; }
    const float* W;
    float* C;
    if (blockIdx.z == 0)      { W = Wq; C = g_Q; }
    else if (blockIdx.z == 1) { W = Wk; C = g_K; }
    else                      { W = Wv; C = g_V; }
    gemm_tf32_body(x, W, C);
}

__global__ void __launch_bounds__(256)
k_gemm_out(const float* __restrict__ Wo, float* __restrict__ out) {
    gemm_tf32_body(g_G, Wo, out);
}

// ---------------------------------------------------------------------------
// RoPE + sigmoid + head-major transpose + Ksum (blocks 0..511)
// Per-head compaction: deterministic ballot scan (blocks 512..519)
// ---------------------------------------------------------------------------
__global__ void __launch_bounds__(256)
k_rope_sig(const float* __restrict__ fc, const float* __restrict__ fs) {
    const int t = threadIdx.x;

    if (blockIdx.x >= S_) {
        // ---- compaction for head h ----
        const int h = blockIdx.x - S_;
        const int lane = t & 31, w = t >> 5;
        __shared__ int swc[16];
        const int s0 = t, s1 = t + 256;
        const int f0 = (g_gate[s0][h] != 0.f) ? 1 : 0;
        const int f1 = (g_gate[s1][h] != 0.f) ? 1 : 0;
        const unsigned b0 = __ballot_sync(0xFFFFFFFFu, f0);
        const unsigned b1 = __ballot_sync(0xFFFFFFFFu, f1);
        if (lane == 0) { swc[w] = __popc(b0); swc[8 + w] = __popc(b1); }
        __syncthreads();
        int pre0 = 0, tot0 = 0;
#pragma unroll
        for (int i = 0; i < 8; i++) {
            if (i < w) pre0 += swc[i];
            tot0 += swc[i];
        }
        int pre1 = tot0;
#pragma unroll
        for (int i = 0; i < 8; i++) if (i < w) pre1 += swc[8 + i];
        const unsigned lm = (1u << lane) - 1u;
        if (f0) g_qidx[h][pre0 + __popc(b0 & lm)] = s0;
        if (f1) g_qidx[h][pre1 + __popc(b1 & lm)] = s1;
        if (t == 0) {
            int tot = tot0;
#pragma unroll
            for (int i = 0; i < 8; i++) tot += swc[8 + i];
            g_qcnt[h] = tot;
        }
        return;
    }

    const int s = blockIdx.x;
    const int h = t >> 5, p = t & 31;

    const float c  = fc[s * HALF_ + p];
    const float sn = fs[s * HALF_ + p];
    const int base = s * DM_ + h * DH_ + 2 * p;

    float q0 = g_Q[base], q1 = g_Q[base + 1];
    float k0 = g_K[base], k1 = g_K[base + 1];
    float qr0 = q0 * c - q1 * sn, qr1 = q0 * sn + q1 * c;
    float kr0 = k0 * c - k1 * sn, kr1 = k0 * sn + k1 * c;
    float ks0 = sigf(kr0), ks1 = sigf(kr1);
    g_Qs[h][s][2 * p]     = sigf(qr0);
    g_Qs[h][s][2 * p + 1] = sigf(qr1);
    g_Ks[h][s][2 * p]     = ks0;
    g_Ks[h][s][2 * p + 1] = ks1;

    float v = ks0 + ks1;
#pragma unroll
    for (int o = 16; o > 0; o >>= 1)
        v += __shfl_xor_sync(0xFFFFFFFFu, v, o);
    if (p == 0) g_Ksum[h][s] = v;

#pragma unroll
    for (int j = t; j < DM_; j += 256) {
        int h2 = j >> 6, d = j & 63;
        g_Vh[h2][s][d] = g_V[s * DM_ + j];
    }
}

// ---------------------------------------------------------------------------
// Attention: 128 threads, 16 compacted queries, split-K x NSPL.
// truth[q,k] = 1 - (sum_d max(Qs,Ks) - Ksum_k)/64
// ---------------------------------------------------------------------------
__global__ void __launch_bounds__(128)
k_attn() {
    const int h   = blockIdx.y;
    const int cnt = g_qcnt[h];
    const int q0  = blockIdx.x * QT;
    if (q0 >= cnt) return;
    const int nq  = min(QT, cnt - q0);
    const int z   = blockIdx.z;
    const int t   = threadIdx.x;

    __shared__ float Qs_s[QT][68];
    __shared__ float Ks_s[32][68];
    __shared__ float Vs_s[32][68];
    __shared__ float Tr  [QT][33];
    __shared__ float rs_s[QT];
    __shared__ float ksum_s[32];
    __shared__ int   sidx[QT];

    if (t < QT) {
        sidx[t] = g_qidx[h][q0 + ((t < nq) ? t : 0)];   // dup-pad tail
        rs_s[t] = 0.f;
    }
    __syncthreads();

#pragma unroll
    for (int j = t; j < QT * 16; j += 128) {
        int r = j >> 4, c4 = (j & 15) << 2;
        *(float4*)&Qs_s[r][c4] = *(const float4*)&g_Qs[h][sidx[r]][c4];
    }

    const int qq = t >> 4, kk = t & 15;     // truth 2q x 2k microtile
    const int qa = 2 * qq, qb = qa + 1;
    const int ka = 2 * kk, kb = ka + 1;

    const int qf = t >> 3;                  // AV: query row (0..15)
    const int dg = (t & 7) << 3;            // AV: 8-dim group
    float acc[8] = {};
    const bool qf_active = (qf < nq);

    for (int kt = 0; kt < KPS / 32; kt++) {
        const int k0 = z * KPS + kt * 32;
        __syncthreads();
#pragma unroll
        for (int j = t; j < 32 * 16; j += 128) {
            int r = j >> 4, c4 = (j & 15) << 2;
            *(float4*)&Ks_s[r][c4] = *(const float4*)&g_Ks[h][k0 + r][c4];
            *(float4*)&Vs_s[r][c4] = *(const float4*)&g_Vh[h][k0 + r][c4];
        }
        if (t < 32) ksum_s[t] = g_Ksum[h][k0 + t];
        __syncthreads();

        {
            float s00 = 0.f, s01 = 0.f, s10 = 0.f, s11 = 0.f;
#pragma unroll
            for (int d = 0; d < 64; d += 4) {
                float4 A0 = *(const float4*)&Qs_s[qa][d];
                float4 A1 = *(const float4*)&Qs_s[qb][d];
                float4 B0 = *(const float4*)&Ks_s[ka][d];
                float4 B1 = *(const float4*)&Ks_s[kb][d];
                s00 += fmaxf(A0.x, B0.x) + fmaxf(A0.y, B0.y)
                     + fmaxf(A0.z, B0.z) + fmaxf(A0.w, B0.w);
                s01 += fmaxf(A0.x, B1.x) + fmaxf(A0.y, B1.y)
                     + fmaxf(A0.z, B1.z) + fmaxf(A0.w, B1.w);
                s10 += fmaxf(A1.x, B0.x) + fmaxf(A1.y, B0.y)
                     + fmaxf(A1.z, B0.z) + fmaxf(A1.w, B0.w);
                s11 += fmaxf(A1.x, B1.x) + fmaxf(A1.y, B1.y)
                     + fmaxf(A1.z, B1.z) + fmaxf(A1.w, B1.w);
            }
            const float c = 1.0f / 64.0f;
            const float ksa = ksum_s[ka], ksb = ksum_s[kb];
            Tr[qa][ka] = 1.0f - (s00 - ksa) * c;
            Tr[qa][kb] = 1.0f - (s01 - ksb) * c;
            Tr[qb][ka] = 1.0f - (s10 - ksa) * c;
            Tr[qb][kb] = 1.0f - (s11 - ksb) * c;
        }
        __syncthreads();

        if (t < QT) {
            float r = 0.f;
#pragma unroll
            for (int k = 0; k < 32; k++) r += Tr[t][k];
            rs_s[t] += r;
        }

#pragma unroll
        for (int k = 0; k < 32; k++) {
            float tv = Tr[qf][k];
            float4 v0 = *(const float4*)&Vs_s[k][dg];
            float4 v1 = *(const float4*)&Vs_s[k][dg + 4];
            acc[0] = fmaf(tv, v0.x, acc[0]);
            acc[1] = fmaf(tv, v0.y, acc[1]);
            acc[2] = fmaf(tv, v0.z, acc[2]);
            acc[3] = fmaf(tv, v0.w, acc[3]);
            acc[4] = fmaf(tv, v1.x, acc[4]);
            acc[5] = fmaf(tv, v1.y, acc[5]);
            acc[6] = fmaf(tv, v1.z, acc[6]);
            acc[7] = fmaf(tv, v1.w, acc[7]);
        }
    }
    __syncthreads();

    if (qf_active) {
        const int s = sidx[qf];
        *(float4*)&g_pacc[z][s][h * DH_ + dg] =
            make_float4(acc[0], acc[1], acc[2], acc[3]);
        *(float4*)&g_pacc[z][s][h * DH_ + dg + 4] =
            make_float4(acc[4], acc[5], acc[6], acc[7]);
    }
    if (t < nq) g_prs[z][sidx[t]][h] = rs_s[t];
}

// ---------------------------------------------------------------------------
// Combine splits + gate -> G
// ---------------------------------------------------------------------------
__global__ void __launch_bounds__(256)
k_norm() {
    const int s = blockIdx.x;
    const int t = threadIdx.x;
#pragma unroll
    for (int j = t; j < DM_; j += 256) {
        int h = j >> 6;
        float gate = g_gate[s][h];
        float v = 0.f;
        if (gate != 0.f) {
            float rs = 0.f, a = 0.f;
#pragma unroll
            for (int z = 0; z < NSPL; z++) {
                rs += g_prs[z][s][h];
                a  += g_pacc[z][s][j];
            }
            v = a * gate / (rs + 1e-9f);
        }
        g_G[s * DM_ + j] = v;
    }
}

// ---------------------------------------------------------------------------
extern "C" void kernel_launch(void* const* d_in, const int* in_sizes, int n_in,
                              void* d_out, int out_size) {
    const float* x  = (const float*)d_in[0];
    const float* fc = (const float*)d_in[1];
    const float* fs = (const float*)d_in[2];
    const float* Wq = (const float*)d_in[3];
    const float* Wk = (const float*)d_in[4];
    const float* Wv = (const float*)d_in[5];
    const float* Wo = (const float*)d_in[6];
    const float* Wr = (const float*)d_in[7];
    float* out = (float*)d_out;

    k_gemm_qkv<<<dim3(8, 8, 4), 256>>>(x, Wq, Wk, Wv, Wr);
    k_rope_sig<<<S_ + H_, 256>>>(fc, fs);
    k_attn    <<<dim3(S_ / QT, H_, NSPL), 128>>>();
    k_norm    <<<S_, 256>>>();
    k_gemm_out<<<dim3(8, 8), 256>>>(Wo, out);
}

// round 11
// speedup vs baseline: 1.4190x; 1.0821x over previous
#include <cuda_runtime.h>

// ---------------------------------------------------------------------------
// MultiUniverseToposAttention  B=1 S=512 H=8 DH=64 DM=512 TOP_K=2
//   1) k_gemm_qkv (z=0..2): Q,K,V = x @ sig(W)^T via 3xTF32 mma.sync
//      (z=3): router gates (logits -> softmax -> top2), reads x only
//   2) k_rope_sig (grid 520): blocks 0..511 RoPE+sigmoid -> head-major
//      Qs,Ks,Vh + Ksum; blocks 512..519 per-head ballot-scan compaction
//   3) k_attn (128 thr, 16-q tiles, split-K x8): truth = 1-(summax-Ksum)/64
//   4) k_norm (float4, MLP8): combine splits + gate -> G
//   5) k_gemm_out: out = G @ sig(Wo)^T  (3xTF32)
// GEMM inner loop: hi/lo tf32 split precomputed at STS time (4 smem planes),
// consumer is pure LDS + MMA.
// ---------------------------------------------------------------------------

#define S_    512
#define DM_   512
#define H_    8
#define DH_   64
#define HALF_ 32
#define NSPL  8
#define KPS   (S_ / NSPL)
#define QT    16

__device__ float g_Q [S_ * DM_];
__device__ float g_K [S_ * DM_];
__device__ float g_V [S_ * DM_];
__device__ float g_Qs[H_][S_][DH_];
__device__ float g_Ks[H_][S_][DH_];
__device__ float g_Vh[H_][S_][DH_];
__device__ float g_Ksum[H_][S_];
__device__ float g_gate[S_][H_];
__device__ int   g_qidx[H_][S_];
__device__ int   g_qcnt[H_];
__device__ float g_G [S_ * DM_];
__device__ float g_pacc[NSPL][S_][DM_];
__device__ float g_prs [NSPL][S_][H_];

__device__ __forceinline__ float sigf(float x) {
    return 1.0f / (1.0f + __expf(-x));
}
__device__ __forceinline__ unsigned f2tf(float x) {
    unsigned u;
    asm("cvt.rna.tf32.f32 %0, %1;" : "=r"(u) : "f"(x));
    return u;
}
__device__ __forceinline__ void hilo(float v, float& h, float& l) {
    unsigned hu = f2tf(v);
    h = __uint_as_float(hu);
    l = __uint_as_float(f2tf(v - h));
}
__device__ __forceinline__ void mma_tf32(float c[4], const unsigned a[4],
                                         const unsigned b[2]) {
    asm volatile(
        "mma.sync.aligned.m16n8k8.row.col.f32.tf32.tf32.f32 "
        "{%0,%1,%2,%3}, {%4,%5,%6,%7}, {%8,%9}, {%0,%1,%2,%3};"
        : "+f"(c[0]), "+f"(c[1]), "+f"(c[2]), "+f"(c[3])
        : "r"(a[0]), "r"(a[1]), "r"(a[2]), "r"(a[3]), "r"(b[0]), "r"(b[1]));
}

// ---------------------------------------------------------------------------
// 3xTF32 GEMM: C = A @ sig(W)^T; 64x64 tile, BK=32, 256 thr (2m x 4n warps).
// hi/lo split done ONCE at STS; fragment LDS layout validated in R9
// (stride 36 -> bank (4*row+tg)%32, all lanes distinct).
// ---------------------------------------------------------------------------
__device__ __forceinline__ void gemm_tf32_body(const float* __restrict__ A,
                                               const float* __restrict__ W,
                                               float* __restrict__ C) {
    __shared__ float Ah[64][36];
    __shared__ float Al[64][36];
    __shared__ float Bh[64][36];
    __shared__ float Bl[64][36];

    const int t    = threadIdx.x;
    const int lane = t & 31, w = t >> 5;
    const int wm = w & 1, wn = w >> 1;
    const int g  = lane >> 2, tg = lane & 3;
    const int m0 = blockIdx.y * 64, n0 = blockIdx.x * 64;

    const int rowL = t >> 2;
    const int cL   = (t & 3) << 3;

    float4 pa0, pa1, pb0, pb1;
    {
        const float* Ar = A + (m0 + rowL) * DM_;
        const float* Wr = W + (n0 + rowL) * DM_;
        pa0 = *(const float4*)&Ar[cL];
        pa1 = *(const float4*)&Ar[cL + 4];
        pb0 = *(const float4*)&Wr[cL];
        pb1 = *(const float4*)&Wr[cL + 4];
    }

    float acc[2][2][4] = {};

    for (int ch = 0; ch < 16; ch++) {
        __syncthreads();
        {
            float4 h4, l4;
            hilo(pa0.x, h4.x, l4.x); hilo(pa0.y, h4.y, l4.y);
            hilo(pa0.z, h4.z, l4.z); hilo(pa0.w, h4.w, l4.w);
            *(float4*)&Ah[rowL][cL] = h4;
            *(float4*)&Al[rowL][cL] = l4;
            hilo(pa1.x, h4.x, l4.x); hilo(pa1.y, h4.y, l4.y);
            hilo(pa1.z, h4.z, l4.z); hilo(pa1.w, h4.w, l4.w);
            *(float4*)&Ah[rowL][cL + 4] = h4;
            *(float4*)&Al[rowL][cL + 4] = l4;
            hilo(sigf(pb0.x), h4.x, l4.x); hilo(sigf(pb0.y), h4.y, l4.y);
            hilo(sigf(pb0.z), h4.z, l4.z); hilo(sigf(pb0.w), h4.w, l4.w);
            *(float4*)&Bh[rowL][cL] = h4;
            *(float4*)&Bl[rowL][cL] = l4;
            hilo(sigf(pb1.x), h4.x, l4.x); hilo(sigf(pb1.y), h4.y, l4.y);
            hilo(sigf(pb1.z), h4.z, l4.z); hilo(sigf(pb1.w), h4.w, l4.w);
            *(float4*)&Bh[rowL][cL + 4] = h4;
            *(float4*)&Bl[rowL][cL + 4] = l4;
        }
        __syncthreads();

        if (ch < 15) {
            const int k0 = (ch + 1) * 32;
            const float* Ar = A + (m0 + rowL) * DM_ + k0;
            const float* Wr = W + (n0 + rowL) * DM_ + k0;
            pa0 = *(const float4*)&Ar[cL];
            pa1 = *(const float4*)&Ar[cL + 4];
            pb0 = *(const float4*)&Wr[cL];
            pb1 = *(const float4*)&Wr[cL + 4];
        }

#pragma unroll
        for (int ks = 0; ks < 4; ks++) {
            const int kb = ks * 8;
            unsigned ah[2][4], al[2][4];
#pragma unroll
            for (int i = 0; i < 2; i++) {
                const int rm = wm * 32 + i * 16 + g;
                ah[i][0] = __float_as_uint(Ah[rm    ][kb + tg]);
                ah[i][1] = __float_as_uint(Ah[rm + 8][kb + tg]);
                ah[i][2] = __float_as_uint(Ah[rm    ][kb + tg + 4]);
                ah[i][3] = __float_as_uint(Ah[rm + 8][kb + tg + 4]);
                al[i][0] = __float_as_uint(Al[rm    ][kb + tg]);
                al[i][1] = __float_as_uint(Al[rm + 8][kb + tg]);
                al[i][2] = __float_as_uint(Al[rm    ][kb + tg + 4]);
                al[i][3] = __float_as_uint(Al[rm + 8][kb + tg + 4]);
            }
            unsigned bh[2][2], bl[2][2];
#pragma unroll
            for (int j = 0; j < 2; j++) {
                const int rn = wn * 16 + j * 8 + g;
                bh[j][0] = __float_as_uint(Bh[rn][kb + tg]);
                bh[j][1] = __float_as_uint(Bh[rn][kb + tg + 4]);
                bl[j][0] = __float_as_uint(Bl[rn][kb + tg]);
                bl[j][1] = __float_as_uint(Bl[rn][kb + tg + 4]);
            }
#pragma unroll
            for (int i = 0; i < 2; i++)
#pragma unroll
                for (int j = 0; j < 2; j++) {
                    mma_tf32(acc[i][j], ah[i], bl[j]);
                    mma_tf32(acc[i][j], al[i], bh[j]);
                    mma_tf32(acc[i][j], ah[i], bh[j]);
                }
        }
    }

#pragma unroll
    for (int i = 0; i < 2; i++)
#pragma unroll
        for (int j = 0; j < 2; j++) {
            const int gm = m0 + wm * 32 + i * 16 + g;
            const int gn = n0 + wn * 16 + j * 8 + tg * 2;
            *(float2*)&C[gm * DM_ + gn]       = make_float2(acc[i][j][0], acc[i][j][1]);
            *(float2*)&C[(gm + 8) * DM_ + gn] = make_float2(acc[i][j][2], acc[i][j][3]);
        }
}

// ---------------------------------------------------------------------------
// Router body (z=3): 64 blocks x 8 warps = 512 tokens; warp per token.
// ---------------------------------------------------------------------------
__device__ __forceinline__ void router_body(const float* __restrict__ x,
                                            const float* __restrict__ Wr) {
    const int t = threadIdx.x;
    const int lane = t & 31, w = t >> 5;
    const int s = (blockIdx.y * 8 + blockIdx.x) * 8 + w;

    const float* xs = x + s * DM_;
    float acc[H_] = {};
#pragma unroll 4
    for (int ds = 0; ds < 16; ds++) {
        const int d = lane + 32 * ds;
        const float xv = xs[d];
#pragma unroll
        for (int h = 0; h < H_; h++)
            acc[h] = fmaf(xv, sigf(Wr[h * DM_ + d]), acc[h]);
    }
#pragma unroll
    for (int h = 0; h < H_; h++)
#pragma unroll
        for (int o = 16; o > 0; o >>= 1)
            acc[h] += __shfl_xor_sync(0xFFFFFFFFu, acc[h], o);

    if (lane == 0) {
        float m = acc[0];
#pragma unroll
        for (int i = 1; i < H_; i++) m = fmaxf(m, acc[i]);
        float e[H_];
        float Z = 0.f;
#pragma unroll
        for (int i = 0; i < H_; i++) { e[i] = expf(acc[i] - m); Z += e[i]; }
        int i0 = 0;
#pragma unroll
        for (int i = 1; i < H_; i++) if (e[i] > e[i0]) i0 = i;
        int i1 = (i0 == 0) ? 1 : 0;
#pragma unroll
        for (int i = 0; i < H_; i++) if (i != i0 && e[i] > e[i1]) i1 = i;
        float p0 = e[i0] / Z, p1 = e[i1] / Z;
        float inv = 1.0f / (p0 + p1 + 1e-9f);
#pragma unroll
        for (int i = 0; i < H_; i++) g_gate[s][i] = 0.f;
        g_gate[s][i0] = p0 * inv;
        g_gate[s][i1] = p1 * inv;
    }
}

__global__ void __launch_bounds__(256)
k_gemm_qkv(const float* __restrict__ x,
           const float* __restrict__ Wq,
           const float* __restrict__ Wk,
           const float* __restrict__ Wv,
           const float* __restrict__ Wr) {
    if (blockIdx.z == 3) { router_body(x, Wr); return; }
    const float* W;
    float* C;
    if (blockIdx.z == 0)      { W = Wq; C = g_Q; }
    else if (blockIdx.z == 1) { W = Wk; C = g_K; }
    else                      { W = Wv; C = g_V; }
    gemm_tf32_body(x, W, C);
}

__global__ void __launch_bounds__(256)
k_gemm_out(const float* __restrict__ Wo, float* __restrict__ out) {
    gemm_tf32_body(g_G, Wo, out);
}

// ---------------------------------------------------------------------------
// RoPE + sigmoid + head-major transpose + Ksum (blocks 0..511)
// Per-head compaction: deterministic ballot scan (blocks 512..519)
// ---------------------------------------------------------------------------
__global__ void __launch_bounds__(256)
k_rope_sig(const float* __restrict__ fc, const float* __restrict__ fs) {
    const int t = threadIdx.x;

    if (blockIdx.x >= S_) {
        const int h = blockIdx.x - S_;
        const int lane = t & 31, w = t >> 5;
        __shared__ int swc[16];
        const int s0 = t, s1 = t + 256;
        const int f0 = (g_gate[s0][h] != 0.f) ? 1 : 0;
        const int f1 = (g_gate[s1][h] != 0.f) ? 1 : 0;
        const unsigned b0 = __ballot_sync(0xFFFFFFFFu, f0);
        const unsigned b1 = __ballot_sync(0xFFFFFFFFu, f1);
        if (lane == 0) { swc[w] = __popc(b0); swc[8 + w] = __popc(b1); }
        __syncthreads();
        int pre0 = 0, tot0 = 0;
#pragma unroll
        for (int i = 0; i < 8; i++) {
            if (i < w) pre0 += swc[i];
            tot0 += swc[i];
        }
        int pre1 = tot0;
#pragma unroll
        for (int i = 0; i < 8; i++) if (i < w) pre1 += swc[8 + i];
        const unsigned lm = (1u << lane) - 1u;
        if (f0) g_qidx[h][pre0 + __popc(b0 & lm)] = s0;
        if (f1) g_qidx[h][pre1 + __popc(b1 & lm)] = s1;
        if (t == 0) {
            int tot = tot0;
#pragma unroll
            for (int i = 0; i < 8; i++) tot += swc[8 + i];
            g_qcnt[h] = tot;
        }
        return;
    }

    const int s = blockIdx.x;
    const int h = t >> 5, p = t & 31;

    const float c  = fc[s * HALF_ + p];
    const float sn = fs[s * HALF_ + p];
    const int base = s * DM_ + h * DH_ + 2 * p;

    float q0 = g_Q[base], q1 = g_Q[base + 1];
    float k0 = g_K[base], k1 = g_K[base + 1];
    float qr0 = q0 * c - q1 * sn, qr1 = q0 * sn + q1 * c;
    float kr0 = k0 * c - k1 * sn, kr1 = k0 * sn + k1 * c;
    float ks0 = sigf(kr0), ks1 = sigf(kr1);
    g_Qs[h][s][2 * p]     = sigf(qr0);
    g_Qs[h][s][2 * p + 1] = sigf(qr1);
    g_Ks[h][s][2 * p]     = ks0;
    g_Ks[h][s][2 * p + 1] = ks1;

    float v = ks0 + ks1;
#pragma unroll
    for (int o = 16; o > 0; o >>= 1)
        v += __shfl_xor_sync(0xFFFFFFFFu, v, o);
    if (p == 0) g_Ksum[h][s] = v;

#pragma unroll
    for (int j = t; j < DM_; j += 256) {
        int h2 = j >> 6, d = j & 63;
        g_Vh[h2][s][d] = g_V[s * DM_ + j];
    }
}

// ---------------------------------------------------------------------------
// Attention: 128 threads, 16 compacted queries, split-K x NSPL.
// ---------------------------------------------------------------------------
__global__ void __launch_bounds__(128)
k_attn() {
    const int h   = blockIdx.y;
    const int cnt = g_qcnt[h];
    const int q0  = blockIdx.x * QT;
    if (q0 >= cnt) return;
    const int nq  = min(QT, cnt - q0);
    const int z   = blockIdx.z;
    const int t   = threadIdx.x;

    __shared__ float Qs_s[QT][68];
    __shared__ float Ks_s[32][68];
    __shared__ float Vs_s[32][68];
    __shared__ float Tr  [QT][33];
    __shared__ float rs_s[QT];
    __shared__ float ksum_s[32];
    __shared__ int   sidx[QT];

    if (t < QT) {
        sidx[t] = g_qidx[h][q0 + ((t < nq) ? t : 0)];
        rs_s[t] = 0.f;
    }
    __syncthreads();

#pragma unroll
    for (int j = t; j < QT * 16; j += 128) {
        int r = j >> 4, c4 = (j & 15) << 2;
        *(float4*)&Qs_s[r][c4] = *(const float4*)&g_Qs[h][sidx[r]][c4];
    }

    const int qq = t >> 4, kk = t & 15;
    const int qa = 2 * qq, qb = qa + 1;
    const int ka = 2 * kk, kb = ka + 1;

    const int qf = t >> 3;
    const int dg = (t & 7) << 3;
    float acc[8] = {};
    const bool qf_active = (qf < nq);

    for (int kt = 0; kt < KPS / 32; kt++) {
        const int k0 = z * KPS + kt * 32;
        __syncthreads();
#pragma unroll
        for (int j = t; j < 32 * 16; j += 128) {
            int r = j >> 4, c4 = (j & 15) << 2;
            *(float4*)&Ks_s[r][c4] = *(const float4*)&g_Ks[h][k0 + r][c4];
            *(float4*)&Vs_s[r][c4] = *(const float4*)&g_Vh[h][k0 + r][c4];
        }
        if (t < 32) ksum_s[t] = g_Ksum[h][k0 + t];
        __syncthreads();

        {
            float s00 = 0.f, s01 = 0.f, s10 = 0.f, s11 = 0.f;
#pragma unroll
            for (int d = 0; d < 64; d += 4) {
                float4 A0 = *(const float4*)&Qs_s[qa][d];
                float4 A1 = *(const float4*)&Qs_s[qb][d];
                float4 B0 = *(const float4*)&Ks_s[ka][d];
                float4 B1 = *(const float4*)&Ks_s[kb][d];
                s00 += fmaxf(A0.x, B0.x) + fmaxf(A0.y, B0.y)
                     + fmaxf(A0.z, B0.z) + fmaxf(A0.w, B0.w);
                s01 += fmaxf(A0.x, B1.x) + fmaxf(A0.y, B1.y)
                     + fmaxf(A0.z, B1.z) + fmaxf(A0.w, B1.w);
                s10 += fmaxf(A1.x, B0.x) + fmaxf(A1.y, B0.y)
                     + fmaxf(A1.z, B0.z) + fmaxf(A1.w, B0.w);
                s11 += fmaxf(A1.x, B1.x) + fmaxf(A1.y, B1.y)
                     + fmaxf(A1.z, B1.z) + fmaxf(A1.w, B1.w);
            }
            const float c = 1.0f / 64.0f;
            const float ksa = ksum_s[ka], ksb = ksum_s[kb];
            Tr[qa][ka] = 1.0f - (s00 - ksa) * c;
            Tr[qa][kb] = 1.0f - (s01 - ksb) * c;
            Tr[qb][ka] = 1.0f - (s10 - ksa) * c;
            Tr[qb][kb] = 1.0f - (s11 - ksb) * c;
        }
        __syncthreads();

        if (t < QT) {
            float r = 0.f;
#pragma unroll
            for (int k = 0; k < 32; k++) r += Tr[t][k];
            rs_s[t] += r;
        }

#pragma unroll
        for (int k = 0; k < 32; k++) {
            float tv = Tr[qf][k];
            float4 v0 = *(const float4*)&Vs_s[k][dg];
            float4 v1 = *(const float4*)&Vs_s[k][dg + 4];
            acc[0] = fmaf(tv, v0.x, acc[0]);
            acc[1] = fmaf(tv, v0.y, acc[1]);
            acc[2] = fmaf(tv, v0.z, acc[2]);
            acc[3] = fmaf(tv, v0.w, acc[3]);
            acc[4] = fmaf(tv, v1.x, acc[4]);
            acc[5] = fmaf(tv, v1.y, acc[5]);
            acc[6] = fmaf(tv, v1.z, acc[6]);
            acc[7] = fmaf(tv, v1.w, acc[7]);
        }
    }
    __syncthreads();

    if (qf_active) {
        const int s = sidx[qf];
        *(float4*)&g_pacc[z][s][h * DH_ + dg] =
            make_float4(acc[0], acc[1], acc[2], acc[3]);
        *(float4*)&g_pacc[z][s][h * DH_ + dg + 4] =
            make_float4(acc[4], acc[5], acc[6], acc[7]);
    }
    if (t < nq) g_prs[z][sidx[t]][h] = rs_s[t];
}

// ---------------------------------------------------------------------------
// Combine splits + gate -> G. One float4 per thread; 8 independent
// LDG.128 in flight (MLP 8).
// ---------------------------------------------------------------------------
__global__ void __launch_bounds__(256)
k_norm() {
    const int j4 = blockIdx.x * 256 + threadIdx.x;   // float4 index
    const int s  = j4 >> 7;
    const int j  = (j4 & 127) << 2;
    const int h  = j >> 6;

    const float gate = g_gate[s][h];
    float4 o = make_float4(0.f, 0.f, 0.f, 0.f);
    if (gate != 0.f) {
        float4 a[NSPL];
#pragma unroll
        for (int z = 0; z < NSPL; z++)
            a[z] = *(const float4*)&g_pacc[z][s][j];
        float rs = 0.f;
#pragma unroll
        for (int z = 0; z < NSPL; z++) rs += g_prs[z][s][h];
        float4 sum = a[0];
#pragma unroll
        for (int z = 1; z < NSPL; z++) {
            sum.x += a[z].x; sum.y += a[z].y;
            sum.z += a[z].z; sum.w += a[z].w;
        }
        const float f = gate / (rs + 1e-9f);
        o = make_float4(sum.x * f, sum.y * f, sum.z * f, sum.w * f);
    }
    *(float4*)&g_G[s * DM_ + j] = o;
}

// ---------------------------------------------------------------------------
extern "C" void kernel_launch(void* const* d_in, const int* in_sizes, int n_in,
                              void* d_out, int out_size) {
    const float* x  = (const float*)d_in[0];
    const float* fc = (const float*)d_in[1];
    const float* fs = (const float*)d_in[2];
    const float* Wq = (const float*)d_in[3];
    const float* Wk = (const float*)d_in[4];
    const float* Wv = (const float*)d_in[5];
    const float* Wo = (const float*)d_in[6];
    const float* Wr = (const float*)d_in[7];
    float* out = (float*)d_out;

    k_gemm_qkv<<<dim3(8, 8, 4), 256>>>(x, Wq, Wk, Wv, Wr);
    k_rope_sig<<<S_ + H_, 256>>>(fc, fs);
    k_attn    <<<dim3(S_ / QT, H_, NSPL), 128>>>();
    k_norm    <<<S_ * DM_ / 4 / 256, 256>>>();
    k_gemm_out<<<dim3(8, 8), 256>>>(Wo, out);
}

// round 12
// speedup vs baseline: 1.4199x; 1.0006x over previous
#include <cuda_runtime.h>

// ---------------------------------------------------------------------------
// MultiUniverseToposAttention  B=1 S=512 H=8 DH=64 DM=512 TOP_K=2
//   1) k_gemm_qkv (z=0..2): Q,K,V = x @ sig(W)^T via 3xTF32 mma.sync
//      (z=3): router gates (logits -> softmax -> top2), reads x only
//   2) k_rope_sig (grid 520): blocks 0..511 RoPE+sigmoid -> head-major
//      Qs,Ks,Vh + Ksum; blocks 512..519 per-head ballot-scan compaction
//   3) k_attn (128 thr, 16-q tiles, split-K x8): truth = 1-(summax-Ksum)/64
//   4) k_norm (float4, MLP8): combine splits + gate -> G
//   5) k_gemm_out: out = G @ sig(Wo)^T  (3xTF32)
// GEMM inner loop: hi/lo tf32 split precomputed at STS time (4 smem planes),
// consumer is pure LDS + MMA.
// ---------------------------------------------------------------------------

#define S_    512
#define DM_   512
#define H_    8
#define DH_   64
#define HALF_ 32
#define NSPL  8
#define KPS   (S_ / NSPL)
#define QT    16

__device__ float g_Q [S_ * DM_];
__device__ float g_K [S_ * DM_];
__device__ float g_V [S_ * DM_];
__device__ float g_Qs[H_][S_][DH_];
__device__ float g_Ks[H_][S_][DH_];
__device__ float g_Vh[H_][S_][DH_];
__device__ float g_Ksum[H_][S_];
__device__ float g_gate[S_][H_];
__device__ int   g_qidx[H_][S_];
__device__ int   g_qcnt[H_];
__device__ float g_G [S_ * DM_];
__device__ float g_pacc[NSPL][S_][DM_];
__device__ float g_prs [NSPL][S_][H_];

__device__ __forceinline__ float sigf(float x) {
    return 1.0f / (1.0f + __expf(-x));
}
__device__ __forceinline__ unsigned f2tf(float x) {
    unsigned u;
    asm("cvt.rna.tf32.f32 %0, %1;" : "=r"(u) : "f"(x));
    return u;
}
__device__ __forceinline__ void hilo(float v, float& h, float& l) {
    unsigned hu = f2tf(v);
    h = __uint_as_float(hu);
    l = __uint_as_float(f2tf(v - h));
}
__device__ __forceinline__ void mma_tf32(float c[4], const unsigned a[4],
                                         const unsigned b[2]) {
    asm volatile(
        "mma.sync.aligned.m16n8k8.row.col.f32.tf32.tf32.f32 "
        "{%0,%1,%2,%3}, {%4,%5,%6,%7}, {%8,%9}, {%0,%1,%2,%3};"
        : "+f"(c[0]), "+f"(c[1]), "+f"(c[2]), "+f"(c[3])
        : "r"(a[0]), "r"(a[1]), "r"(a[2]), "r"(a[3]), "r"(b[0]), "r"(b[1]));
}

// ---------------------------------------------------------------------------
// 3xTF32 GEMM: C = A @ sig(W)^T; 64x64 tile, BK=32, 256 thr (2m x 4n warps).
// hi/lo split done ONCE at STS; fragment LDS layout validated in R9
// (stride 36 -> bank (4*row+tg)%32, all lanes distinct).
// ---------------------------------------------------------------------------
__device__ __forceinline__ void gemm_tf32_body(const float* __restrict__ A,
                                               const float* __restrict__ W,
                                               float* __restrict__ C) {
    __shared__ float Ah[64][36];
    __shared__ float Al[64][36];
    __shared__ float Bh[64][36];
    __shared__ float Bl[64][36];

    const int t    = threadIdx.x;
    const int lane = t & 31, w = t >> 5;
    const int wm = w & 1, wn = w >> 1;
    const int g  = lane >> 2, tg = lane & 3;
    const int m0 = blockIdx.y * 64, n0 = blockIdx.x * 64;

    const int rowL = t >> 2;
    const int cL   = (t & 3) << 3;

    float4 pa0, pa1, pb0, pb1;
    {
        const float* Ar = A + (m0 + rowL) * DM_;
        const float* Wr = W + (n0 + rowL) * DM_;
        pa0 = *(const float4*)&Ar[cL];
        pa1 = *(const float4*)&Ar[cL + 4];
        pb0 = *(const float4*)&Wr[cL];
        pb1 = *(const float4*)&Wr[cL + 4];
    }

    float acc[2][2][4] = {};

    for (int ch = 0; ch < 16; ch++) {
        __syncthreads();
        {
            float4 h4, l4;
            hilo(pa0.x, h4.x, l4.x); hilo(pa0.y, h4.y, l4.y);
            hilo(pa0.z, h4.z, l4.z); hilo(pa0.w, h4.w, l4.w);
            *(float4*)&Ah[rowL][cL] = h4;
            *(float4*)&Al[rowL][cL] = l4;
            hilo(pa1.x, h4.x, l4.x); hilo(pa1.y, h4.y, l4.y);
            hilo(pa1.z, h4.z, l4.z); hilo(pa1.w, h4.w, l4.w);
            *(float4*)&Ah[rowL][cL + 4] = h4;
            *(float4*)&Al[rowL][cL + 4] = l4;
            hilo(sigf(pb0.x), h4.x, l4.x); hilo(sigf(pb0.y), h4.y, l4.y);
            hilo(sigf(pb0.z), h4.z, l4.z); hilo(sigf(pb0.w), h4.w, l4.w);
            *(float4*)&Bh[rowL][cL] = h4;
            *(float4*)&Bl[rowL][cL] = l4;
            hilo(sigf(pb1.x), h4.x, l4.x); hilo(sigf(pb1.y), h4.y, l4.y);
            hilo(sigf(pb1.z), h4.z, l4.z); hilo(sigf(pb1.w), h4.w, l4.w);
            *(float4*)&Bh[rowL][cL + 4] = h4;
            *(float4*)&Bl[rowL][cL + 4] = l4;
        }
        __syncthreads();

        if (ch < 15) {
            const int k0 = (ch + 1) * 32;
            const float* Ar = A + (m0 + rowL) * DM_ + k0;
            const float* Wr = W + (n0 + rowL) * DM_ + k0;
            pa0 = *(const float4*)&Ar[cL];
            pa1 = *(const float4*)&Ar[cL + 4];
            pb0 = *(const float4*)&Wr[cL];
            pb1 = *(const float4*)&Wr[cL + 4];
        }

#pragma unroll
        for (int ks = 0; ks < 4; ks++) {
            const int kb = ks * 8;
            unsigned ah[2][4], al[2][4];
#pragma unroll
            for (int i = 0; i < 2; i++) {
                const int rm = wm * 32 + i * 16 + g;
                ah[i][0] = __float_as_uint(Ah[rm    ][kb + tg]);
                ah[i][1] = __float_as_uint(Ah[rm + 8][kb + tg]);
                ah[i][2] = __float_as_uint(Ah[rm    ][kb + tg + 4]);
                ah[i][3] = __float_as_uint(Ah[rm + 8][kb + tg + 4]);
                al[i][0] = __float_as_uint(Al[rm    ][kb + tg]);
                al[i][1] = __float_as_uint(Al[rm + 8][kb + tg]);
                al[i][2] = __float_as_uint(Al[rm    ][kb + tg + 4]);
                al[i][3] = __float_as_uint(Al[rm + 8][kb + tg + 4]);
            }
            unsigned bh[2][2], bl[2][2];
#pragma unroll
            for (int j = 0; j < 2; j++) {
                const int rn = wn * 16 + j * 8 + g;
                bh[j][0] = __float_as_uint(Bh[rn][kb + tg]);
                bh[j][1] = __float_as_uint(Bh[rn][kb + tg + 4]);
                bl[j][0] = __float_as_uint(Bl[rn][kb + tg]);
                bl[j][1] = __float_as_uint(Bl[rn][kb + tg + 4]);
            }
#pragma unroll
            for (int i = 0; i < 2; i++)
#pragma unroll
                for (int j = 0; j < 2; j++) {
                    mma_tf32(acc[i][j], ah[i], bl[j]);
                    mma_tf32(acc[i][j], al[i], bh[j]);
                    mma_tf32(acc[i][j], ah[i], bh[j]);
                }
        }
    }

#pragma unroll
    for (int i = 0; i < 2; i++)
#pragma unroll
        for (int j = 0; j < 2; j++) {
            const int gm = m0 + wm * 32 + i * 16 + g;
            const int gn = n0 + wn * 16 + j * 8 + tg * 2;
            *(float2*)&C[gm * DM_ + gn]       = make_float2(acc[i][j][0], acc[i][j][1]);
            *(float2*)&C[(gm + 8) * DM_ + gn] = make_float2(acc[i][j][2], acc[i][j][3]);
        }
}

// ---------------------------------------------------------------------------
// Router body (z=3): 64 blocks x 8 warps = 512 tokens; warp per token.
// ---------------------------------------------------------------------------
__device__ __forceinline__ void router_body(const float* __restrict__ x,
                                            const float* __restrict__ Wr) {
    const int t = threadIdx.x;
    const int lane = t & 31, w = t >> 5;
    const int s = (blockIdx.y * 8 + blockIdx.x) * 8 + w;

    const float* xs = x + s * DM_;
    float acc[H_] = {};
#pragma unroll 4
    for (int ds = 0; ds < 16; ds++) {
        const int d = lane + 32 * ds;
        const float xv = xs[d];
#pragma unroll
        for (int h = 0; h < H_; h++)
            acc[h] = fmaf(xv, sigf(Wr[h * DM_ + d]), acc[h]);
    }
#pragma unroll
    for (int h = 0; h < H_; h++)
#pragma unroll
        for (int o = 16; o > 0; o >>= 1)
            acc[h] += __shfl_xor_sync(0xFFFFFFFFu, acc[h], o);

    if (lane == 0) {
        float m = acc[0];
#pragma unroll
        for (int i = 1; i < H_; i++) m = fmaxf(m, acc[i]);
        float e[H_];
        float Z = 0.f;
#pragma unroll
        for (int i = 0; i < H_; i++) { e[i] = expf(acc[i] - m); Z += e[i]; }
        int i0 = 0;
#pragma unroll
        for (int i = 1; i < H_; i++) if (e[i] > e[i0]) i0 = i;
        int i1 = (i0 == 0) ? 1 : 0;
#pragma unroll
        for (int i = 0; i < H_; i++) if (i != i0 && e[i] > e[i1]) i1 = i;
        float p0 = e[i0] / Z, p1 = e[i1] / Z;
        float inv = 1.0f / (p0 + p1 + 1e-9f);
#pragma unroll
        for (int i = 0; i < H_; i++) g_gate[s][i] = 0.f;
        g_gate[s][i0] = p0 * inv;
        g_gate[s][i1] = p1 * inv;
    }
}

__global__ void __launch_bounds__(256)
k_gemm_qkv(const float* __restrict__ x,
           const float* __restrict__ Wq,
           const float* __restrict__ Wk,
           const float* __restrict__ Wv,
           const float* __restrict__ Wr) {
    if (blockIdx.z == 3) { router_body(x, Wr); return; }
    const float* W;
    float* C;
    if (blockIdx.z == 0)      { W = Wq; C = g_Q; }
    else if (blockIdx.z == 1) { W = Wk; C = g_K; }
    else                      { W = Wv; C = g_V; }
    gemm_tf32_body(x, W, C);
}

__global__ void __launch_bounds__(256)
k_gemm_out(const float* __restrict__ Wo, float* __restrict__ out) {
    gemm_tf32_body(g_G, Wo, out);
}

// ---------------------------------------------------------------------------
// RoPE + sigmoid + head-major transpose + Ksum (blocks 0..511)
// Per-head compaction: deterministic ballot scan (blocks 512..519)
// ---------------------------------------------------------------------------
__global__ void __launch_bounds__(256)
k_rope_sig(const float* __restrict__ fc, const float* __restrict__ fs) {
    const int t = threadIdx.x;

    if (blockIdx.x >= S_) {
        const int h = blockIdx.x - S_;
        const int lane = t & 31, w = t >> 5;
        __shared__ int swc[16];
        const int s0 = t, s1 = t + 256;
        const int f0 = (g_gate[s0][h] != 0.f) ? 1 : 0;
        const int f1 = (g_gate[s1][h] != 0.f) ? 1 : 0;
        const unsigned b0 = __ballot_sync(0xFFFFFFFFu, f0);
        const unsigned b1 = __ballot_sync(0xFFFFFFFFu, f1);
        if (lane == 0) { swc[w] = __popc(b0); swc[8 + w] = __popc(b1); }
        __syncthreads();
        int pre0 = 0, tot0 = 0;
#pragma unroll
        for (int i = 0; i < 8; i++) {
            if (i < w) pre0 += swc[i];
            tot0 += swc[i];
        }
        int pre1 = tot0;
#pragma unroll
        for (int i = 0; i < 8; i++) if (i < w) pre1 += swc[8 + i];
        const unsigned lm = (1u << lane) - 1u;
        if (f0) g_qidx[h][pre0 + __popc(b0 & lm)] = s0;
        if (f1) g_qidx[h][pre1 + __popc(b1 & lm)] = s1;
        if (t == 0) {
            int tot = tot0;
#pragma unroll
            for (int i = 0; i < 8; i++) tot += swc[8 + i];
            g_qcnt[h] = tot;
        }
        return;
    }

    const int s = blockIdx.x;
    const int h = t >> 5, p = t & 31;

    const float c  = fc[s * HALF_ + p];
    const float sn = fs[s * HALF_ + p];
    const int base = s * DM_ + h * DH_ + 2 * p;

    float q0 = g_Q[base], q1 = g_Q[base + 1];
    float k0 = g_K[base], k1 = g_K[base + 1];
    float qr0 = q0 * c - q1 * sn, qr1 = q0 * sn + q1 * c;
    float kr0 = k0 * c - k1 * sn, kr1 = k0 * sn + k1 * c;
    float ks0 = sigf(kr0), ks1 = sigf(kr1);
    g_Qs[h][s][2 * p]     = sigf(qr0);
    g_Qs[h][s][2 * p + 1] = sigf(qr1);
    g_Ks[h][s][2 * p]     = ks0;
    g_Ks[h][s][2 * p + 1] = ks1;

    float v = ks0 + ks1;
#pragma unroll
    for (int o = 16; o > 0; o >>= 1)
        v += __shfl_xor_sync(0xFFFFFFFFu, v, o);
    if (p == 0) g_Ksum[h][s] = v;

#pragma unroll
    for (int j = t; j < DM_; j += 256) {
        int h2 = j >> 6, d = j & 63;
        g_Vh[h2][s][d] = g_V[s * DM_ + j];
    }
}

// ---------------------------------------------------------------------------
// Attention: 128 threads, 16 compacted queries, split-K x NSPL.
// ---------------------------------------------------------------------------
__global__ void __launch_bounds__(128)
k_attn() {
    const int h   = blockIdx.y;
    const int cnt = g_qcnt[h];
    const int q0  = blockIdx.x * QT;
    if (q0 >= cnt) return;
    const int nq  = min(QT, cnt - q0);
    const int z   = blockIdx.z;
    const int t   = threadIdx.x;

    __shared__ float Qs_s[QT][68];
    __shared__ float Ks_s[32][68];
    __shared__ float Vs_s[32][68];
    __shared__ float Tr  [QT][33];
    __shared__ float rs_s[QT];
    __shared__ float ksum_s[32];
    __shared__ int   sidx[QT];

    if (t < QT) {
        sidx[t] = g_qidx[h][q0 + ((t < nq) ? t : 0)];
        rs_s[t] = 0.f;
    }
    __syncthreads();

#pragma unroll
    for (int j = t; j < QT * 16; j += 128) {
        int r = j >> 4, c4 = (j & 15) << 2;
        *(float4*)&Qs_s[r][c4] = *(const float4*)&g_Qs[h][sidx[r]][c4];
    }

    const int qq = t >> 4, kk = t & 15;
    const int qa = 2 * qq, qb = qa + 1;
    const int ka = 2 * kk, kb = ka + 1;

    const int qf = t >> 3;
    const int dg = (t & 7) << 3;
    float acc[8] = {};
    const bool qf_active = (qf < nq);

    for (int kt = 0; kt < KPS / 32; kt++) {
        const int k0 = z * KPS + kt * 32;
        __syncthreads();
#pragma unroll
        for (int j = t; j < 32 * 16; j += 128) {
            int r = j >> 4, c4 = (j & 15) << 2;
            *(float4*)&Ks_s[r][c4] = *(const float4*)&g_Ks[h][k0 + r][c4];
            *(float4*)&Vs_s[r][c4] = *(const float4*)&g_Vh[h][k0 + r][c4];
        }
        if (t < 32) ksum_s[t] = g_Ksum[h][k0 + t];
        __syncthreads();

        {
            float s00 = 0.f, s01 = 0.f, s10 = 0.f, s11 = 0.f;
#pragma unroll
            for (int d = 0; d < 64; d += 4) {
                float4 A0 = *(const float4*)&Qs_s[qa][d];
                float4 A1 = *(const float4*)&Qs_s[qb][d];
                float4 B0 = *(const float4*)&Ks_s[ka][d];
                float4 B1 = *(const float4*)&Ks_s[kb][d];
                s00 += fmaxf(A0.x, B0.x) + fmaxf(A0.y, B0.y)
                     + fmaxf(A0.z, B0.z) + fmaxf(A0.w, B0.w);
                s01 += fmaxf(A0.x, B1.x) + fmaxf(A0.y, B1.y)
                     + fmaxf(A0.z, B1.z) + fmaxf(A0.w, B1.w);
                s10 += fmaxf(A1.x, B0.x) + fmaxf(A1.y, B0.y)
                     + fmaxf(A1.z, B0.z) + fmaxf(A1.w, B0.w);
                s11 += fmaxf(A1.x, B1.x) + fmaxf(A1.y, B1.y)
                     + fmaxf(A1.z, B1.z) + fmaxf(A1.w, B1.w);
            }
            const float c = 1.0f / 64.0f;
            const float ksa = ksum_s[ka], ksb = ksum_s[kb];
            Tr[qa][ka] = 1.0f - (s00 - ksa) * c;
            Tr[qa][kb] = 1.0f - (s01 - ksb) * c;
            Tr[qb][ka] = 1.0f - (s10 - ksa) * c;
            Tr[qb][kb] = 1.0f - (s11 - ksb) * c;
        }
        __syncthreads();

        if (t < QT) {
            float r = 0.f;
#pragma unroll
            for (int k = 0; k < 32; k++) r += Tr[t][k];
            rs_s[t] += r;
        }

#pragma unroll
        for (int k = 0; k < 32; k++) {
            float tv = Tr[qf][k];
            float4 v0 = *(const float4*)&Vs_s[k][dg];
            float4 v1 = *(const float4*)&Vs_s[k][dg + 4];
            acc[0] = fmaf(tv, v0.x, acc[0]);
            acc[1] = fmaf(tv, v0.y, acc[1]);
            acc[2] = fmaf(tv, v0.z, acc[2]);
            acc[3] = fmaf(tv, v0.w, acc[3]);
            acc[4] = fmaf(tv, v1.x, acc[4]);
            acc[5] = fmaf(tv, v1.y, acc[5]);
            acc[6] = fmaf(tv, v1.z, acc[6]);
            acc[7] = fmaf(tv, v1.w, acc[7]);
        }
    }
    __syncthreads();

    if (qf_active) {
        const int s = sidx[qf];
        *(float4*)&g_pacc[z][s][h * DH_ + dg] =
            make_float4(acc[0], acc[1], acc[2], acc[3]);
        *(float4*)&g_pacc[z][s][h * DH_ + dg + 4] =
            make_float4(acc[4], acc[5], acc[6], acc[7]);
    }
    if (t < nq) g_prs[z][sidx[t]][h] = rs_s[t];
}

// ---------------------------------------------------------------------------
// Combine splits + gate -> G. One float4 per thread; 8 independent
// LDG.128 in flight (MLP 8).
// ---------------------------------------------------------------------------
__global__ void __launch_bounds__(256)
k_norm() {
    const int j4 = blockIdx.x * 256 + threadIdx.x;   // float4 index
    const int s  = j4 >> 7;
    const int j  = (j4 & 127) << 2;
    const int h  = j >> 6;

    const float gate = g_gate[s][h];
    float4 o = make_float4(0.f, 0.f, 0.f, 0.f);
    if (gate != 0.f) {
        float4 a[NSPL];
#pragma unroll
        for (int z = 0; z < NSPL; z++)
            a[z] = *(const float4*)&g_pacc[z][s][j];
        float rs = 0.f;
#pragma unroll
        for (int z = 0; z < NSPL; z++) rs += g_prs[z][s][h];
        float4 sum = a[0];
#pragma unroll
        for (int z = 1; z < NSPL; z++) {
            sum.x += a[z].x; sum.y += a[z].y;
            sum.z += a[z].z; sum.w += a[z].w;
        }
        const float f = gate / (rs + 1e-9f);
        o = make_float4(sum.x * f, sum.y * f, sum.z * f, sum.w * f);
    }
    *(float4*)&g_G[s * DM_ + j] = o;
}

// ---------------------------------------------------------------------------
extern "C" void kernel_launch(void* const* d_in, const int* in_sizes, int n_in,
                              void* d_out, int out_size) {
    const float* x  = (const float*)d_in[0];
    const float* fc = (const float*)d_in[1];
    const float* fs = (const float*)d_in[2];
    const float* Wq = (const float*)d_in[3];
    const float* Wk = (const float*)d_in[4];
    const float* Wv = (const float*)d_in[5];
    const float* Wo = (const float*)d_in[6];
    const float* Wr = (const float*)d_in[7];
    float* out = (float*)d_out;

    k_gemm_qkv<<<dim3(8, 8, 4), 256>>>(x, Wq, Wk, Wv, Wr);
    k_rope_sig<<<S_ + H_, 256>>>(fc, fs);
    k_attn    <<<dim3(S_ / QT, H_, NSPL), 128>>>();
    k_norm    <<<S_ * DM_ / 4 / 256, 256>>>();
    k_gemm_out<<<dim3(8, 8), 256>>>(Wo, out);
}

// round 14
// speedup vs baseline: 1.7314x; 1.2194x over previous
#include <cuda_runtime.h>

// ---------------------------------------------------------------------------
// MultiUniverseToposAttention  B=1 S=512 H=8 DH=64 DM=512 TOP_K=2
//   1) k_gemm_qkv (z=0..2): Q,K,V = x @ sig(W)^T via 3xTF32 mma.sync
//      (z=3): router gates (logits -> softmax -> top2), reads x only
//   2) k_rope_sig (grid 520+256): RoPE+sigmoid -> head-major Qs,Ks,Vh + Ksum;
//      per-head ballot-scan compaction; tail blocks zero `out`
//   3) k_attn (128 thr, 16-q tiles, split-K x8): truth = 1-(summax-Ksum)/64
//   4) k_norm: combine splits + gate -> compact Gc[h][slot][64] (active only)
//   5) k_gemm_out_sp: per-head gather-GEMM (K=64), scatter-atomicAdd epilogue
//      (exactly 2 commutative fp32 adds per output element -> deterministic)
// ---------------------------------------------------------------------------

#define S_    512
#define DM_   512
#define H_    8
#define DH_   64
#define HALF_ 32
#define NSPL  8
#define KPS   (S_ / NSPL)
#define QT    16

__device__ float g_Q [S_ * DM_];
__device__ float g_K [S_ * DM_];
__device__ float g_V [S_ * DM_];
__device__ float g_Qs[H_][S_][DH_];
__device__ float g_Ks[H_][S_][DH_];
__device__ float g_Vh[H_][S_][DH_];
__device__ float g_Ksum[H_][S_];
__device__ float g_gate[S_][H_];
__device__ int   g_qidx[H_][S_];
__device__ int   g_qcnt[H_];
__device__ float g_Gc[H_][S_][DH_];        // compacted gated attn output
__device__ float g_pacc[NSPL][S_][DM_];
__device__ float g_prs [NSPL][S_][H_];

__device__ __forceinline__ float sigf(float x) {
    return 1.0f / (1.0f + __expf(-x));
}
__device__ __forceinline__ unsigned f2tf(float x) {
    unsigned u;
    asm("cvt.rna.tf32.f32 %0, %1;" : "=r"(u) : "f"(x));
    return u;
}
__device__ __forceinline__ void hilo(float v, float& h, float& l) {
    unsigned hu = f2tf(v);
    h = __uint_as_float(hu);
    l = __uint_as_float(f2tf(v - h));
}
__device__ __forceinline__ void mma_tf32(float c[4], const unsigned a[4],
                                         const unsigned b[2]) {
    asm volatile(
        "mma.sync.aligned.m16n8k8.row.col.f32.tf32.tf32.f32 "
        "{%0,%1,%2,%3}, {%4,%5,%6,%7}, {%8,%9}, {%0,%1,%2,%3};"
        : "+f"(c[0]), "+f"(c[1]), "+f"(c[2]), "+f"(c[3])
        : "r"(a[0]), "r"(a[1]), "r"(a[2]), "r"(a[3]), "r"(b[0]), "r"(b[1]));
}

// ---------------------------------------------------------------------------
// Dense 3xTF32 GEMM (R11-validated): C = A @ sig(W)^T; 64x64 tile, BK=32.
// hi/lo split at STS time into 4 smem planes; consumer pure LDS+MMA.
// ---------------------------------------------------------------------------
__device__ __forceinline__ void gemm_tf32_body(const float* __restrict__ A,
                                               const float* __restrict__ W,
                                               float* __restrict__ C) {
    __shared__ float Ah[64][36];
    __shared__ float Al[64][36];
    __shared__ float Bh[64][36];
    __shared__ float Bl[64][36];

    const int t    = threadIdx.x;
    const int lane = t & 31, w = t >> 5;
    const int wm = w & 1, wn = w >> 1;
    const int g  = lane >> 2, tg = lane & 3;
    const int m0 = blockIdx.y * 64, n0 = blockIdx.x * 64;

    const int rowL = t >> 2;
    const int cL   = (t & 3) << 3;

    float4 pa0, pa1, pb0, pb1;
    {
        const float* Ar = A + (m0 + rowL) * DM_;
        const float* Wr = W + (n0 + rowL) * DM_;
        pa0 = *(const float4*)&Ar[cL];
        pa1 = *(const float4*)&Ar[cL + 4];
        pb0 = *(const float4*)&Wr[cL];
        pb1 = *(const float4*)&Wr[cL + 4];
    }

    float acc[2][2][4] = {};

    for (int ch = 0; ch < 16; ch++) {
        __syncthreads();
        {
            float4 h4, l4;
            hilo(pa0.x, h4.x, l4.x); hilo(pa0.y, h4.y, l4.y);
            hilo(pa0.z, h4.z, l4.z); hilo(pa0.w, h4.w, l4.w);
            *(float4*)&Ah[rowL][cL] = h4;
            *(float4*)&Al[rowL][cL] = l4;
            hilo(pa1.x, h4.x, l4.x); hilo(pa1.y, h4.y, l4.y);
            hilo(pa1.z, h4.z, l4.z); hilo(pa1.w, h4.w, l4.w);
            *(float4*)&Ah[rowL][cL + 4] = h4;
            *(float4*)&Al[rowL][cL + 4] = l4;
            hilo(sigf(pb0.x), h4.x, l4.x); hilo(sigf(pb0.y), h4.y, l4.y);
            hilo(sigf(pb0.z), h4.z, l4.z); hilo(sigf(pb0.w), h4.w, l4.w);
            *(float4*)&Bh[rowL][cL] = h4;
            *(float4*)&Bl[rowL][cL] = l4;
            hilo(sigf(pb1.x), h4.x, l4.x); hilo(sigf(pb1.y), h4.y, l4.y);
            hilo(sigf(pb1.z), h4.z, l4.z); hilo(sigf(pb1.w), h4.w, l4.w);
            *(float4*)&Bh[rowL][cL + 4] = h4;
            *(float4*)&Bl[rowL][cL + 4] = l4;
        }
        __syncthreads();

        if (ch < 15) {
            const int k0 = (ch + 1) * 32;
            const float* Ar = A + (m0 + rowL) * DM_ + k0;
            const float* Wr = W + (n0 + rowL) * DM_ + k0;
            pa0 = *(const float4*)&Ar[cL];
            pa1 = *(const float4*)&Ar[cL + 4];
            pb0 = *(const float4*)&Wr[cL];
            pb1 = *(const float4*)&Wr[cL + 4];
        }

#pragma unroll
        for (int ks = 0; ks < 4; ks++) {
            const int kb = ks * 8;
            unsigned ah[2][4], al[2][4];
#pragma unroll
            for (int i = 0; i < 2; i++) {
                const int rm = wm * 32 + i * 16 + g;
                ah[i][0] = __float_as_uint(Ah[rm    ][kb + tg]);
                ah[i][1] = __float_as_uint(Ah[rm + 8][kb + tg]);
                ah[i][2] = __float_as_uint(Ah[rm    ][kb + tg + 4]);
                ah[i][3] = __float_as_uint(Ah[rm + 8][kb + tg + 4]);
                al[i][0] = __float_as_uint(Al[rm    ][kb + tg]);
                al[i][1] = __float_as_uint(Al[rm + 8][kb + tg]);
                al[i][2] = __float_as_uint(Al[rm    ][kb + tg + 4]);
                al[i][3] = __float_as_uint(Al[rm + 8][kb + tg + 4]);
            }
            unsigned bh[2][2], bl[2][2];
#pragma unroll
            for (int j = 0; j < 2; j++) {
                const int rn = wn * 16 + j * 8 + g;
                bh[j][0] = __float_as_uint(Bh[rn][kb + tg]);
                bh[j][1] = __float_as_uint(Bh[rn][kb + tg + 4]);
                bl[j][0] = __float_as_uint(Bl[rn][kb + tg]);
                bl[j][1] = __float_as_uint(Bl[rn][kb + tg + 4]);
            }
#pragma unroll
            for (int i = 0; i < 2; i++)
#pragma unroll
                for (int j = 0; j < 2; j++) {
                    mma_tf32(acc[i][j], ah[i], bl[j]);
                    mma_tf32(acc[i][j], al[i], bh[j]);
                    mma_tf32(acc[i][j], ah[i], bh[j]);
                }
        }
    }

#pragma unroll
    for (int i = 0; i < 2; i++)
#pragma unroll
        for (int j = 0; j < 2; j++) {
            const int gm = m0 + wm * 32 + i * 16 + g;
            const int gn = n0 + wn * 16 + j * 8 + tg * 2;
            *(float2*)&C[gm * DM_ + gn]       = make_float2(acc[i][j][0], acc[i][j][1]);
            *(float2*)&C[(gm + 8) * DM_ + gn] = make_float2(acc[i][j][2], acc[i][j][3]);
        }
}

// ---------------------------------------------------------------------------
// Router body (z=3): 64 blocks x 8 warps = 512 tokens; warp per token.
// ---------------------------------------------------------------------------
__device__ __forceinline__ void router_body(const float* __restrict__ x,
                                            const float* __restrict__ Wr) {
    const int t = threadIdx.x;
    const int lane = t & 31, w = t >> 5;
    const int s = (blockIdx.y * 8 + blockIdx.x) * 8 + w;

    const float* xs = x + s * DM_;
    float acc[H_] = {};
#pragma unroll 4
    for (int ds = 0; ds < 16; ds++) {
        const int d = lane + 32 * ds;
        const float xv = xs[d];
#pragma unroll
        for (int h = 0; h < H_; h++)
            acc[h] = fmaf(xv, sigf(Wr[h * DM_ + d]), acc[h]);
    }
#pragma unroll
    for (int h = 0; h < H_; h++)
#pragma unroll
        for (int o = 16; o > 0; o >>= 1)
            acc[h] += __shfl_xor_sync(0xFFFFFFFFu, acc[h], o);

    if (lane == 0) {
        float m = acc[0];
#pragma unroll
        for (int i = 1; i < H_; i++) m = fmaxf(m, acc[i]);
        float e[H_];
        float Z = 0.f;
#pragma unroll
        for (int i = 0; i < H_; i++) { e[i] = expf(acc[i] - m); Z += e[i]; }
        int i0 = 0;
#pragma unroll
        for (int i = 1; i < H_; i++) if (e[i] > e[i0]) i0 = i;
        int i1 = (i0 == 0) ? 1 : 0;
#pragma unroll
        for (int i = 0; i < H_; i++) if (i != i0 && e[i] > e[i1]) i1 = i;
        float p0 = e[i0] / Z, p1 = e[i1] / Z;
        float inv = 1.0f / (p0 + p1 + 1e-9f);
#pragma unroll
        for (int i = 0; i < H_; i++) g_gate[s][i] = 0.f;
        g_gate[s][i0] = p0 * inv;
        g_gate[s][i1] = p1 * inv;
    }
}

__global__ void __launch_bounds__(256)
k_gemm_qkv(const float* __restrict__ x,
           const float* __restrict__ Wq,
           const float* __restrict__ Wk,
           const float* __restrict__ Wv,
           const float* __restrict__ Wr) {
    if (blockIdx.z == 3) { router_body(x, Wr); return; }
    const float* W;
    float* C;
    if (blockIdx.z == 0)      { W = Wq; C = g_Q; }
    else if (blockIdx.z == 1) { W = Wk; C = g_K; }
    else                      { W = Wv; C = g_V; }
    gemm_tf32_body(x, W, C);
}

// ---------------------------------------------------------------------------
// RoPE + sigmoid + head-major transpose + Ksum (blocks 0..511)
// Per-head compaction (blocks 512..519); zero `out` (blocks 520..775)
// ---------------------------------------------------------------------------
__global__ void __launch_bounds__(256)
k_rope_sig(const float* __restrict__ fc, const float* __restrict__ fs,
           float* __restrict__ out) {
    const int t = threadIdx.x;

    if (blockIdx.x >= S_ + H_) {
        const int zb = blockIdx.x - (S_ + H_);
        *(float4*)&out[(zb * 256 + t) * 4] = make_float4(0.f, 0.f, 0.f, 0.f);
        return;
    }

    if (blockIdx.x >= S_) {
        const int h = blockIdx.x - S_;
        const int lane = t & 31, w = t >> 5;
        __shared__ int swc[16];
        const int s0 = t, s1 = t + 256;
        const int f0 = (g_gate[s0][h] != 0.f) ? 1 : 0;
        const int f1 = (g_gate[s1][h] != 0.f) ? 1 : 0;
        const unsigned b0 = __ballot_sync(0xFFFFFFFFu, f0);
        const unsigned b1 = __ballot_sync(0xFFFFFFFFu, f1);
        if (lane == 0) { swc[w] = __popc(b0); swc[8 + w] = __popc(b1); }
        __syncthreads();
        int pre0 = 0, tot0 = 0;
#pragma unroll
        for (int i = 0; i < 8; i++) {
            if (i < w) pre0 += swc[i];
            tot0 += swc[i];
        }
        int pre1 = tot0;
#pragma unroll
        for (int i = 0; i < 8; i++) if (i < w) pre1 += swc[8 + i];
        const unsigned lm = (1u << lane) - 1u;
        if (f0) g_qidx[h][pre0 + __popc(b0 & lm)] = s0;
        if (f1) g_qidx[h][pre1 + __popc(b1 & lm)] = s1;
        if (t == 0) {
            int tot = tot0;
#pragma unroll
            for (int i = 0; i < 8; i++) tot += swc[8 + i];
            g_qcnt[h] = tot;
        }
        return;
    }

    const int s = blockIdx.x;
    const int h = t >> 5, p = t & 31;

    const float c  = fc[s * HALF_ + p];
    const float sn = fs[s * HALF_ + p];
    const int base = s * DM_ + h * DH_ + 2 * p;

    float q0 = g_Q[base], q1 = g_Q[base + 1];
    float k0 = g_K[base], k1 = g_K[base + 1];
    float qr0 = q0 * c - q1 * sn, qr1 = q0 * sn + q1 * c;
    float kr0 = k0 * c - k1 * sn, kr1 = k0 * sn + k1 * c;
    float ks0 = sigf(kr0), ks1 = sigf(kr1);
    g_Qs[h][s][2 * p]     = sigf(qr0);
    g_Qs[h][s][2 * p + 1] = sigf(qr1);
    g_Ks[h][s][2 * p]     = ks0;
    g_Ks[h][s][2 * p + 1] = ks1;

    float v = ks0 + ks1;
#pragma unroll
    for (int o = 16; o > 0; o >>= 1)
        v += __shfl_xor_sync(0xFFFFFFFFu, v, o);
    if (p == 0) g_Ksum[h][s] = v;

#pragma unroll
    for (int j = t; j < DM_; j += 256) {
        int h2 = j >> 6, d = j & 63;
        g_Vh[h2][s][d] = g_V[s * DM_ + j];
    }
}

// ---------------------------------------------------------------------------
// Attention: 128 threads, 16 compacted queries, split-K x NSPL.
// ---------------------------------------------------------------------------
__global__ void __launch_bounds__(128)
k_attn() {
    const int h   = blockIdx.y;
    const int cnt = g_qcnt[h];
    const int q0  = blockIdx.x * QT;
    if (q0 >= cnt) return;
    const int nq  = min(QT, cnt - q0);
    const int z   = blockIdx.z;
    const int t   = threadIdx.x;

    __shared__ float Qs_s[QT][68];
    __shared__ float Ks_s[32][68];
    __shared__ float Vs_s[32][68];
    __shared__ float Tr  [QT][33];
    __shared__ float rs_s[QT];
    __shared__ float ksum_s[32];
    __shared__ int   sidx[QT];

    if (t < QT) {
        sidx[t] = g_qidx[h][q0 + ((t < nq) ? t : 0)];
        rs_s[t] = 0.f;
    }
    __syncthreads();

#pragma unroll
    for (int j = t; j < QT * 16; j += 128) {
        int r = j >> 4, c4 = (j & 15) << 2;
        *(float4*)&Qs_s[r][c4] = *(const float4*)&g_Qs[h][sidx[r]][c4];
    }

    const int qq = t >> 4, kk = t & 15;
    const int qa = 2 * qq, qb = qa + 1;
    const int ka = 2 * kk, kb = ka + 1;

    const int qf = t >> 3;
    const int dg = (t & 7) << 3;
    float acc[8] = {};
    const bool qf_active = (qf < nq);

    for (int kt = 0; kt < KPS / 32; kt++) {
        const int k0 = z * KPS + kt * 32;
        __syncthreads();
#pragma unroll
        for (int j = t; j < 32 * 16; j += 128) {
            int r = j >> 4, c4 = (j & 15) << 2;
            *(float4*)&Ks_s[r][c4] = *(const float4*)&g_Ks[h][k0 + r][c4];
            *(float4*)&Vs_s[r][c4] = *(const float4*)&g_Vh[h][k0 + r][c4];
        }
        if (t < 32) ksum_s[t] = g_Ksum[h][k0 + t];
        __syncthreads();

        {
            float s00 = 0.f, s01 = 0.f, s10 = 0.f, s11 = 0.f;
#pragma unroll
            for (int d = 0; d < 64; d += 4) {
                float4 A0 = *(const float4*)&Qs_s[qa][d];
                float4 A1 = *(const float4*)&Qs_s[qb][d];
                float4 B0 = *(const float4*)&Ks_s[ka][d];
                float4 B1 = *(const float4*)&Ks_s[kb][d];
                s00 += fmaxf(A0.x, B0.x) + fmaxf(A0.y, B0.y)
                     + fmaxf(A0.z, B0.z) + fmaxf(A0.w, B0.w);
                s01 += fmaxf(A0.x, B1.x) + fmaxf(A0.y, B1.y)
                     + fmaxf(A0.z, B1.z) + fmaxf(A0.w, B1.w);
                s10 += fmaxf(A1.x, B0.x) + fmaxf(A1.y, B0.y)
                     + fmaxf(A1.z, B0.z) + fmaxf(A1.w, B0.w);
                s11 += fmaxf(A1.x, B1.x) + fmaxf(A1.y, B1.y)
                     + fmaxf(A1.z, B1.z) + fmaxf(A1.w, B1.w);
            }
            const float c = 1.0f / 64.0f;
            const float ksa = ksum_s[ka], ksb = ksum_s[kb];
            Tr[qa][ka] = 1.0f - (s00 - ksa) * c;
            Tr[qa][kb] = 1.0f - (s01 - ksb) * c;
            Tr[qb][ka] = 1.0f - (s10 - ksa) * c;
            Tr[qb][kb] = 1.0f - (s11 - ksb) * c;
        }
        __syncthreads();

        if (t < QT) {
            float r = 0.f;
#pragma unroll
            for (int k = 0; k < 32; k++) r += Tr[t][k];
            rs_s[t] += r;
        }

#pragma unroll
        for (int k = 0; k < 32; k++) {
            float tv = Tr[qf][k];
            float4 v0 = *(const float4*)&Vs_s[k][dg];
            float4 v1 = *(const float4*)&Vs_s[k][dg + 4];
            acc[0] = fmaf(tv, v0.x, acc[0]);
            acc[1] = fmaf(tv, v0.y, acc[1]);
            acc[2] = fmaf(tv, v0.z, acc[2]);
            acc[3] = fmaf(tv, v0.w, acc[3]);
            acc[4] = fmaf(tv, v1.x, acc[4]);
            acc[5] = fmaf(tv, v1.y, acc[5]);
            acc[6] = fmaf(tv, v1.z, acc[6]);
            acc[7] = fmaf(tv, v1.w, acc[7]);
        }
    }
    __syncthreads();

    if (qf_active) {
        const int s = sidx[qf];
        *(float4*)&g_pacc[z][s][h * DH_ + dg] =
            make_float4(acc[0], acc[1], acc[2], acc[3]);
        *(float4*)&g_pacc[z][s][h * DH_ + dg + 4] =
            make_float4(acc[4], acc[5], acc[6], acc[7]);
    }
    if (t < nq) g_prs[z][sidx[t]][h] = rs_s[t];
}

// ---------------------------------------------------------------------------
// Combine splits + gate -> compact Gc[h][slot][d]  (active pairs only).
// Block = 16 slots x 16 float4-threads; grid (32, 8).
// ---------------------------------------------------------------------------
__global__ void __launch_bounds__(256)
k_norm() {
    const int h   = blockIdx.y;
    const int cnt = g_qcnt[h];
    const int q0  = blockIdx.x * 16;
    if (q0 >= cnt) return;
    const int t  = threadIdx.x;
    const int sl = q0 + (t >> 4);
    if (sl >= cnt) return;
    const int d = (t & 15) << 2;
    const int s = g_qidx[h][sl];

    float rs = 0.f;
#pragma unroll
    for (int z = 0; z < NSPL; z++) rs += g_prs[z][s][h];
    float4 sum = make_float4(0.f, 0.f, 0.f, 0.f);
#pragma unroll
    for (int z = 0; z < NSPL; z++) {
        float4 a = *(const float4*)&g_pacc[z][s][h * DH_ + d];
        sum.x += a.x; sum.y += a.y; sum.z += a.z; sum.w += a.w;
    }
    const float f = g_gate[s][h] / (rs + 1e-9f);
    *(float4*)&g_Gc[h][sl][d] =
        make_float4(sum.x * f, sum.y * f, sum.z * f, sum.w * f);
}

// ---------------------------------------------------------------------------
// Sparse output GEMM: out[s][n] += sum_k Gc[h][slot][k] * sig(Wo[n][h*64+k])
// per head, gathered rows, K=64 (2 BK=32 chunks), scatter-atomicAdd epilogue.
// Grid (8 n-tiles, 8 slot-tiles, 8 heads), 256 thr. Pad rows computed but
// skipped at epilogue (Gc garbage is finite).
// ---------------------------------------------------------------------------
__global__ void __launch_bounds__(256)
k_gemm_out_sp(const float* __restrict__ Wo, float* __restrict__ out) {
    const int h   = blockIdx.z;
    const int cnt = g_qcnt[h];
    const int m0  = blockIdx.y * 64;
    if (m0 >= cnt) return;
    const int n0  = blockIdx.x * 64;

    __shared__ float As[64][36];
    __shared__ float Bs[64][36];

    const int t    = threadIdx.x;
    const int lane = t & 31, w = t >> 5;
    const int wm = w & 1, wn = w >> 1;
    const int g  = lane >> 2, tg = lane & 3;
    const int rowL = t >> 2;
    const int cL   = (t & 3) << 3;

    float acc[2][2][4] = {};

    for (int ch = 0; ch < 2; ch++) {
        const int k0 = ch * 32;
        const int rA = min(m0 + rowL, S_ - 1);
        const float* Ar = &g_Gc[h][rA][k0 + cL];
        const float* Wr = Wo + (n0 + rowL) * DM_ + h * DH_ + k0 + cL;
        float4 a0 = *(const float4*)Ar;
        float4 a1 = *(const float4*)(Ar + 4);
        float4 b0 = *(const float4*)Wr;
        float4 b1 = *(const float4*)(Wr + 4);
        __syncthreads();
        *(float4*)&As[rowL][cL]     = a0;
        *(float4*)&As[rowL][cL + 4] = a1;
        *(float4*)&Bs[rowL][cL] =
            make_float4(sigf(b0.x), sigf(b0.y), sigf(b0.z), sigf(b0.w));
        *(float4*)&Bs[rowL][cL + 4] =
            make_float4(sigf(b1.x), sigf(b1.y), sigf(b1.z), sigf(b1.w));
        __syncthreads();

#pragma unroll
        for (int ks = 0; ks < 4; ks++) {
            const int kb = ks * 8;
            unsigned ah[2][4], al[2][4];
#pragma unroll
            for (int i = 0; i < 2; i++) {
                const int rm = wm * 32 + i * 16 + g;
                float v0 = As[rm    ][kb + tg];
                float v1 = As[rm + 8][kb + tg];
                float v2 = As[rm    ][kb + tg + 4];
                float v3 = As[rm + 8][kb + tg + 4];
                float hh, ll;
                hilo(v0, hh, ll); ah[i][0] = __float_as_uint(hh); al[i][0] = __float_as_uint(ll);
                hilo(v1, hh, ll); ah[i][1] = __float_as_uint(hh); al[i][1] = __float_as_uint(ll);
                hilo(v2, hh, ll); ah[i][2] = __float_as_uint(hh); al[i][2] = __float_as_uint(ll);
                hilo(v3, hh, ll); ah[i][3] = __float_as_uint(hh); al[i][3] = __float_as_uint(ll);
            }
            unsigned bh[2][2], bl[2][2];
#pragma unroll
            for (int j = 0; j < 2; j++) {
                const int rn = wn * 16 + j * 8 + g;
                float v0 = Bs[rn][kb + tg];
                float v1 = Bs[rn][kb + tg + 4];
                float hh, ll;
                hilo(v0, hh, ll); bh[j][0] = __float_as_uint(hh); bl[j][0] = __float_as_uint(ll);
                hilo(v1, hh, ll); bh[j][1] = __float_as_uint(hh); bl[j][1] = __float_as_uint(ll);
            }
#pragma unroll
            for (int i = 0; i < 2; i++)
#pragma unroll
                for (int j = 0; j < 2; j++) {
                    mma_tf32(acc[i][j], ah[i], bl[j]);
                    mma_tf32(acc[i][j], al[i], bh[j]);
                    mma_tf32(acc[i][j], ah[i], bh[j]);
                }
        }
    }

    // scatter epilogue: atomicAdd into out rows g_qidx[h][slot]
#pragma unroll
    for (int i = 0; i < 2; i++)
#pragma unroll
        for (int j = 0; j < 2; j++) {
            const int sl0 = m0 + wm * 32 + i * 16 + g;
            const int sl1 = sl0 + 8;
            const int gn  = n0 + wn * 16 + j * 8 + tg * 2;
            if (sl0 < cnt) {
                const int s = g_qidx[h][sl0];
                atomicAdd(&out[s * DM_ + gn],     acc[i][j][0]);
                atomicAdd(&out[s * DM_ + gn + 1], acc[i][j][1]);
            }
            if (sl1 < cnt) {
                const int s = g_qidx[h][sl1];
                atomicAdd(&out[s * DM_ + gn],     acc[i][j][2]);
                atomicAdd(&out[s * DM_ + gn + 1], acc[i][j][3]);
            }
        }
}

// ---------------------------------------------------------------------------
extern "C" void kernel_launch(void* const* d_in, const int* in_sizes, int n_in,
                              void* d_out, int out_size) {
    const float* x  = (const float*)d_in[0];
    const float* fc = (const float*)d_in[1];
    const float* fs = (const float*)d_in[2];
    const float* Wq = (const float*)d_in[3];
    const float* Wk = (const float*)d_in[4];
    const float* Wv = (const float*)d_in[5];
    const float* Wo = (const float*)d_in[6];
    const float* Wr = (const float*)d_in[7];
    float* out = (float*)d_out;

    k_gemm_qkv   <<<dim3(8, 8, 4), 256>>>(x, Wq, Wk, Wv, Wr);
    k_rope_sig   <<<S_ + H_ + 256, 256>>>(fc, fs, out);
    k_attn       <<<dim3(S_ / QT, H_, NSPL), 128>>>();
    k_norm       <<<dim3(32, H_), 256>>>();
    k_gemm_out_sp<<<dim3(8, 8, H_), 256>>>(Wo, out);
}